// round 6
// baseline (speedup 1.0000x reference)
#include <cuda_runtime.h>
#include <cuda_bf16.h>
#include <mma.h>
#include <cstdint>

using namespace nvcuda;
typedef __nv_bfloat16 bf16;

#define DIM    512
#define NH     16
#define HD     32
#define NWIN   512      // 8 batches * 8*8 windows
#define NTOK   32768    // 512 windows * 64 tokens
#define NQKV   1536
#define WSCALE 0.17677669529663687f   // 32^-0.5

// GEMM tiling: BM=128 rows, two 64-wide column subtiles per CTA (eff BN=128)
#define BM 128
#define BK 32
#define SA 40   // A smem row stride (bf16 elems)
#define SB 72   // B smem row stride (bf16 elems)
#define SC 68   // C epilogue stride (f32)

// Scratch (allocation-free __device__ globals)
__device__ float g_q[(size_t)NWIN * NH * 64 * HD];
__device__ float g_k[(size_t)NWIN * NH * 64 * HD];
__device__ float g_v[(size_t)NWIN * NH * 64 * HD];
__device__ float g_ao[(size_t)NTOK * DIM];
// pre-split weights (uint4 type => guaranteed 16B alignment)
__device__ uint4 g_wqh[(size_t)DIM * NQKV / 8];
__device__ uint4 g_wql[(size_t)DIM * NQKV / 8];
__device__ uint4 g_wph[(size_t)DIM * DIM / 8];
__device__ uint4 g_wpl[(size_t)DIM * DIM / 8];

__device__ __forceinline__ unsigned short us(bf16 v) { return __bfloat16_as_ushort(v); }

// split float4 -> packed bf16 hi pair-of-uint / lo pair-of-uint
__device__ __forceinline__ void split_pack(float4 v, uint2& ph, uint2& pl) {
    bf16 h0 = __float2bfloat16(v.x), h1 = __float2bfloat16(v.y);
    bf16 h2 = __float2bfloat16(v.z), h3 = __float2bfloat16(v.w);
    bf16 l0 = __float2bfloat16(v.x - __bfloat162float(h0));
    bf16 l1 = __float2bfloat16(v.y - __bfloat162float(h1));
    bf16 l2 = __float2bfloat16(v.z - __bfloat162float(h2));
    bf16 l3 = __float2bfloat16(v.w - __bfloat162float(h3));
    ph.x = us(h0) | ((unsigned)us(h1) << 16);
    ph.y = us(h2) | ((unsigned)us(h3) << 16);
    pl.x = us(l0) | ((unsigned)us(l1) << 16);
    pl.y = us(l2) | ((unsigned)us(l3) << 16);
}

// windowed row index -> global token index
__device__ __forceinline__ int win_token(int r) {
    int wid = r >> 6, n = r & 63;
    int b = wid >> 6, wy = (wid >> 3) & 7, wx = wid & 7;
    int h = wy * 8 + (n >> 3), w = wx * 8 + (n & 7);
    return (b << 12) + (h << 6) + w;
}

// pre-split a weight matrix into bf16 hi/lo (one uint4 = 8 outputs per thread)
__global__ void split_w_kernel(const float* __restrict__ w, uint4* __restrict__ hi,
                               uint4* __restrict__ lo) {
    int idx = blockIdx.x * 256 + threadIdx.x;     // uint4 index
    float4 v0 = *reinterpret_cast<const float4*>(w + (size_t)idx * 8);
    float4 v1 = *reinterpret_cast<const float4*>(w + (size_t)idx * 8 + 4);
    uint2 ph0, pl0, ph1, pl1;
    split_pack(v0, ph0, pl0);
    split_pack(v1, ph1, pl1);
    hi[idx] = make_uint4(ph0.x, ph0.y, ph1.x, ph1.y);
    lo[idx] = make_uint4(pl0.x, pl0.y, pl1.x, pl1.y);
}

// C = A @ W + bias, compensated bf16 (hh+hl+lh), fp32 accum.
// One CTA: 128 rows x (2 x 64) cols. A split in-kernel (shared by both subtiles);
// W pre-split (pure uint4 copy into smem).
template<int NCOLS, bool REMAP_IN, bool QKV_EPI>
__global__ void gemm_kernel(const float* __restrict__ A,
                            const bf16* __restrict__ Whi,
                            const bf16* __restrict__ Wlo,
                            const float* __restrict__ bias,
                            float* __restrict__ out)
{
    extern __shared__ __align__(16) char smraw[];
    bf16* smb = reinterpret_cast<bf16*>(smraw);
    // bf16-elem offsets: a_hi 0 (5120), a_lo 5120, b0_hi 10240 (2304), b0_lo 12544,
    //                    b1_hi 14848, b1_lo 17152 (end 19456 = 38912 B)

    const float* Asrc = REMAP_IN ? A : g_ao;

    int tid  = threadIdx.x;
    int warp = tid >> 5;
    int wm = warp >> 1, wn = warp & 1;
    int rbase = blockIdx.x * BM;
    int nbase = blockIdx.y * 128;

    wmma::fragment<wmma::accumulator, 16, 16, 16, float> acc[2][2][2];
    #pragma unroll
    for (int sb = 0; sb < 2; sb++)
        #pragma unroll
        for (int i = 0; i < 2; i++)
            #pragma unroll
            for (int j = 0; j < 2; j++) wmma::fill_fragment(acc[sb][i][j], 0.0f);

    int brow = tid >> 3, bc4 = tid & 7;   // B copy coords: 32 rows x 8 uint4

    for (int kt = 0; kt < DIM / BK; kt++) {
        __syncthreads();
        // A tile: 128 rows x 32 cols f32 -> split to hi/lo (8 float4/row)
        #pragma unroll
        for (int s4 = 0; s4 < 4; s4++) {
            int idx = tid + s4 * 256;
            int i = idx >> 3, c = idx & 7;
            int r = rbase + i;
            int t = REMAP_IN ? win_token(r) : r;
            float4 v = *reinterpret_cast<const float4*>(
                Asrc + (size_t)t * DIM + kt * BK + c * 4);
            uint2 ph, pl; split_pack(v, ph, pl);
            *reinterpret_cast<uint2*>(smb + i * SA + c * 4)        = ph;
            *reinterpret_cast<uint2*>(smb + 5120 + i * SA + c * 4) = pl;
        }
        // B tiles: pure uint4 copies from pre-split weights (2 subtiles x hi/lo)
        #pragma unroll
        for (int sb = 0; sb < 2; sb++) {
            size_t goff = (size_t)(kt * BK + brow) * NCOLS + nbase + sb * 64 + bc4 * 8;
            int so = 10240 + sb * 4608 + brow * SB + bc4 * 8;
            *reinterpret_cast<uint4*>(smb + so) =
                *reinterpret_cast<const uint4*>(Whi + goff);
            *reinterpret_cast<uint4*>(smb + so + 2304) =
                *reinterpret_cast<const uint4*>(Wlo + goff);
        }
        __syncthreads();
        #pragma unroll
        for (int ks = 0; ks < 2; ks++) {
            wmma::fragment<wmma::matrix_a, 16, 16, 16, bf16, wmma::row_major> fah[2], fal[2];
            #pragma unroll
            for (int i = 0; i < 2; i++) {
                int row = wm * 32 + i * 16;
                wmma::load_matrix_sync(fah[i], smb + row * SA + ks * 16, SA);
                wmma::load_matrix_sync(fal[i], smb + 5120 + row * SA + ks * 16, SA);
            }
            #pragma unroll
            for (int sb = 0; sb < 2; sb++) {
                wmma::fragment<wmma::matrix_b, 16, 16, 16, bf16, wmma::row_major> fbh[2], fbl[2];
                #pragma unroll
                for (int j = 0; j < 2; j++) {
                    int col = wn * 32 + j * 16;
                    int bo = 10240 + sb * 4608;
                    wmma::load_matrix_sync(fbh[j], smb + bo + (ks * 16) * SB + col, SB);
                    wmma::load_matrix_sync(fbl[j], smb + bo + 2304 + (ks * 16) * SB + col, SB);
                }
                #pragma unroll
                for (int i = 0; i < 2; i++)
                    #pragma unroll
                    for (int j = 0; j < 2; j++) {
                        wmma::mma_sync(acc[sb][i][j], fah[i], fbh[j], acc[sb][i][j]);
                        wmma::mma_sync(acc[sb][i][j], fah[i], fbl[j], acc[sb][i][j]);
                        wmma::mma_sync(acc[sb][i][j], fal[i], fbh[j], acc[sb][i][j]);
                    }
            }
        }
    }

    // Epilogue: two passes (one per 64-col subtile) through a 128x68 f32 smem stage
    float* csm = reinterpret_cast<float*>(smraw);
    #pragma unroll
    for (int sb = 0; sb < 2; sb++) {
        __syncthreads();
        #pragma unroll
        for (int i = 0; i < 2; i++)
            #pragma unroll
            for (int j = 0; j < 2; j++)
                wmma::store_matrix_sync(csm + (wm * 32 + i * 16) * SC + wn * 32 + j * 16,
                                        acc[sb][i][j], SC, wmma::mem_row_major);
        __syncthreads();

        for (int s4 = 0; s4 < (BM * 64) / 256; s4++) {
            int idx = tid + s4 * 256;
            int i = idx >> 6, cl = idx & 63;
            int r = rbase + i;
            int c = nbase + sb * 64 + cl;
            float v = csm[i * SC + cl] + bias[c];
            if (QKV_EPI) {
                int wid = r >> 6, n = r & 63;
                int which = c >> 9;           // 0=q 1=k 2=v
                int cc = c & 511;
                int head = cc >> 5, d = cc & 31;
                float o;
                if (which < 2) {
                    // axial 2D RoPE: dims 0..15 rotate with row pos, 16..31 with col pos
                    int j16 = d & 15;
                    int g   = d >> 4;
                    int pos = g ? (n & 7) : (n >> 3);
                    int jj  = j16 & 7;
                    float invf = exp2f(-1.6609640474436813f * (float)jj); // 10000^(-jj/8)
                    float ang = (float)pos * invf;
                    float sn, cs;
                    sincosf(ang, &sn, &cs);
                    int off = (j16 < 8) ? 8 : -8;
                    float vp = csm[i * SC + cl + off] + bias[c + off];
                    o = (j16 < 8) ? (v * cs - vp * sn) : (v * cs + vp * sn);
                } else {
                    o = v;
                }
                float* dst = (which == 0) ? g_q : (which == 1) ? g_k : g_v;
                dst[(((size_t)wid * NH + head) * 64 + n) * HD + d] = o;
            } else {
                int t = win_token(r);
                out[(size_t)t * DIM + c] = v;
            }
        }
    }
}

// One CTA per (window, head): S = (Q*scale) K^T, softmax, O = A V.
// Compensated bf16 MMA; f32 in/out globals. Softmax parallelized 4 threads/row.
__global__ void attn_kernel()
{
    extern __shared__ __align__(16) char smraw[];
    bf16* smb = reinterpret_cast<bf16*>(smraw);
    // bf16-elem offsets: qh 0, ql 2560, kh 5120, kl 7680, vh 10240, vl 12800
    float* s = reinterpret_cast<float*>(smraw + 30720);   // 64x68 f32
    bf16* ah = smb;                                        // overlay over q/k (dead after S)
    bf16* al = smb + 4608;

    int tid = threadIdx.x, warp = tid >> 5;
    int wid = blockIdx.x, head = blockIdx.y;
    size_t base = ((size_t)wid * NH + head) * (64 * HD);
    const float* qg = g_q + base;
    const float* kg = g_k + base;
    const float* vg = g_v + base;

    #pragma unroll
    for (int s4 = 0; s4 < 2; s4++) {
        int e = tid + s4 * 256;
        int n = e >> 3, d4 = e & 7;
        float4 v; uint2 ph, pl;
        v = *reinterpret_cast<const float4*>(qg + e * 4);
        v.x *= WSCALE; v.y *= WSCALE; v.z *= WSCALE; v.w *= WSCALE;
        split_pack(v, ph, pl);
        *reinterpret_cast<uint2*>(smb + n * SA + d4 * 4)        = ph;
        *reinterpret_cast<uint2*>(smb + 2560 + n * SA + d4 * 4) = pl;
        v = *reinterpret_cast<const float4*>(kg + e * 4);
        split_pack(v, ph, pl);
        *reinterpret_cast<uint2*>(smb + 5120 + n * SA + d4 * 4) = ph;
        *reinterpret_cast<uint2*>(smb + 7680 + n * SA + d4 * 4) = pl;
        v = *reinterpret_cast<const float4*>(vg + e * 4);
        split_pack(v, ph, pl);
        *reinterpret_cast<uint2*>(smb + 10240 + n * SA + d4 * 4) = ph;
        *reinterpret_cast<uint2*>(smb + 12800 + n * SA + d4 * 4) = pl;
    }
    __syncthreads();

    // S = Q K^T : 16 frags of 16x16, 2 per warp
    #pragma unroll
    for (int fi = 0; fi < 2; fi++) {
        int f = warp + fi * 8;
        int mi = f >> 2, ni = f & 3;
        wmma::fragment<wmma::accumulator, 16, 16, 16, float> acc;
        wmma::fill_fragment(acc, 0.0f);
        #pragma unroll
        for (int ks = 0; ks < 2; ks++) {
            wmma::fragment<wmma::matrix_a, 16, 16, 16, bf16, wmma::row_major> fah, fal;
            wmma::fragment<wmma::matrix_b, 16, 16, 16, bf16, wmma::col_major> fbh, fbl;
            wmma::load_matrix_sync(fah, smb + (mi * 16) * SA + ks * 16, SA);
            wmma::load_matrix_sync(fal, smb + 2560 + (mi * 16) * SA + ks * 16, SA);
            wmma::load_matrix_sync(fbh, smb + 5120 + (ni * 16) * SA + ks * 16, SA);
            wmma::load_matrix_sync(fbl, smb + 7680 + (ni * 16) * SA + ks * 16, SA);
            wmma::mma_sync(acc, fah, fbh, acc);
            wmma::mma_sync(acc, fah, fbl, acc);
            wmma::mma_sync(acc, fal, fbh, acc);
        }
        wmma::store_matrix_sync(s + (mi * 16) * SC + ni * 16, acc, SC, wmma::mem_row_major);
    }
    __syncthreads();

    // Row softmax: 4 threads per row (consecutive lanes), shfl reduce
    {
        int row = tid >> 2, l4 = tid & 3;
        float* sr = s + row * SC;
        float m = -1e30f;
        #pragma unroll
        for (int c = 0; c < 16; c++) m = fmaxf(m, sr[l4 * 16 + c]);
        m = fmaxf(m, __shfl_xor_sync(0xFFFFFFFF, m, 1));
        m = fmaxf(m, __shfl_xor_sync(0xFFFFFFFF, m, 2));
        float sum = 0.f;
        float e[16];
        #pragma unroll
        for (int c = 0; c < 16; c++) { e[c] = expf(sr[l4 * 16 + c] - m); sum += e[c]; }
        sum += __shfl_xor_sync(0xFFFFFFFF, sum, 1);
        sum += __shfl_xor_sync(0xFFFFFFFF, sum, 2);
        float inv = 1.f / sum;
        #pragma unroll
        for (int c = 0; c < 16; c++) {
            float a = e[c] * inv;
            bf16 h = __float2bfloat16(a);
            ah[row * SB + l4 * 16 + c] = h;
            al[row * SB + l4 * 16 + c] = __float2bfloat16(a - __bfloat162float(h));
        }
    }
    __syncthreads();

    // O = A V : 8 frags (4x2), one per warp; store f32 direct to g_ao
    {
        int mi = warp >> 1, ni = warp & 1;
        wmma::fragment<wmma::accumulator, 16, 16, 16, float> acc;
        wmma::fill_fragment(acc, 0.0f);
        #pragma unroll
        for (int ks = 0; ks < 4; ks++) {
            wmma::fragment<wmma::matrix_a, 16, 16, 16, bf16, wmma::row_major> fah, fal;
            wmma::fragment<wmma::matrix_b, 16, 16, 16, bf16, wmma::row_major> fbh, fbl;
            wmma::load_matrix_sync(fah, ah + (mi * 16) * SB + ks * 16, SB);
            wmma::load_matrix_sync(fal, al + (mi * 16) * SB + ks * 16, SB);
            wmma::load_matrix_sync(fbh, smb + 10240 + (ks * 16) * SA + ni * 16, SA);
            wmma::load_matrix_sync(fbl, smb + 12800 + (ks * 16) * SA + ni * 16, SA);
            wmma::mma_sync(acc, fah, fbh, acc);
            wmma::mma_sync(acc, fah, fbl, acc);
            wmma::mma_sync(acc, fal, fbh, acc);
        }
        wmma::store_matrix_sync(
            g_ao + (size_t)(wid * 64 + mi * 16) * DIM + head * HD + ni * 16,
            acc, DIM, wmma::mem_row_major);
    }
}

extern "C" void kernel_launch(void* const* d_in, const int* in_sizes, int n_in,
                              void* d_out, int out_size)
{
    (void)in_sizes; (void)n_in; (void)out_size;
    const float* x      = (const float*)d_in[0];
    const float* qkv_w  = (const float*)d_in[1];
    const float* qkv_b  = (const float*)d_in[2];
    // d_in[3], d_in[4] (kv_w, kv_b) are dead code in the reference output
    const float* proj_w = (const float*)d_in[5];
    const float* proj_b = (const float*)d_in[6];
    float* out = (float*)d_out;

    const int gemm_smem = 38912;                  // tiles 38912 B; csm pass 34816 B
    const int attn_smem = 30720 + 64 * SC * 4;    // 48128 B (< 48KB default limit)

    split_w_kernel<<<DIM * NQKV / 8 / 256, 256>>>(qkv_w, g_wqh, g_wql);
    split_w_kernel<<<DIM * DIM / 8 / 256, 256>>>(proj_w, g_wph, g_wpl);

    gemm_kernel<NQKV, true, true>
        <<<dim3(NTOK / BM, NQKV / 128), 256, gemm_smem>>>(
            x, (const bf16*)g_wqh, (const bf16*)g_wql, qkv_b, nullptr);
    attn_kernel<<<dim3(NWIN, NH), 256, attn_smem>>>();
    gemm_kernel<DIM, false, false>
        <<<dim3(NTOK / BM, DIM / 128), 256, gemm_smem>>>(
            nullptr, (const bf16*)g_wph, (const bf16*)g_wpl, proj_b, out);
}

// round 7
// speedup vs baseline: 2.0558x; 2.0558x over previous
#include <cuda_runtime.h>
#include <cuda_bf16.h>
#include <mma.h>
#include <cstdint>

using namespace nvcuda;
typedef __nv_bfloat16 bf16;

#define DIM    512
#define NH     16
#define HD     32
#define NWIN   512      // 8 batches * 8*8 windows
#define NTOK   32768    // 512 windows * 64 tokens
#define NQKV   1536
#define WSCALE 0.17677669529663687f   // 32^-0.5

// GEMM tiling (R4-proven shape)
#define BM 128
#define BN 64
#define BK 32
#define SA 40   // A smem row stride (bf16 elems)
#define SB 72   // B smem row stride (bf16 elems)
#define SC 68   // C epilogue stride (f32)

// Scratch (allocation-free __device__ globals)
__device__ float g_q[(size_t)NWIN * NH * 64 * HD];
__device__ float g_k[(size_t)NWIN * NH * 64 * HD];
__device__ float g_v[(size_t)NWIN * NH * 64 * HD];
__device__ float g_ao[(size_t)NTOK * DIM];
// pre-split weights (uint4 type => guaranteed 16B alignment)
__device__ uint4 g_wqh[(size_t)DIM * NQKV / 8];
__device__ uint4 g_wql[(size_t)DIM * NQKV / 8];
__device__ uint4 g_wph[(size_t)DIM * DIM / 8];
__device__ uint4 g_wpl[(size_t)DIM * DIM / 8];

__device__ __forceinline__ unsigned short us(bf16 v) { return __bfloat16_as_ushort(v); }

// split float4 -> packed bf16 hi pair-of-uint / lo pair-of-uint
__device__ __forceinline__ void split_pack(float4 v, uint2& ph, uint2& pl) {
    bf16 h0 = __float2bfloat16(v.x), h1 = __float2bfloat16(v.y);
    bf16 h2 = __float2bfloat16(v.z), h3 = __float2bfloat16(v.w);
    bf16 l0 = __float2bfloat16(v.x - __bfloat162float(h0));
    bf16 l1 = __float2bfloat16(v.y - __bfloat162float(h1));
    bf16 l2 = __float2bfloat16(v.z - __bfloat162float(h2));
    bf16 l3 = __float2bfloat16(v.w - __bfloat162float(h3));
    ph.x = us(h0) | ((unsigned)us(h1) << 16);
    ph.y = us(h2) | ((unsigned)us(h3) << 16);
    pl.x = us(l0) | ((unsigned)us(l1) << 16);
    pl.y = us(l2) | ((unsigned)us(l3) << 16);
}

// windowed row index -> global token index
__device__ __forceinline__ int win_token(int r) {
    int wid = r >> 6, n = r & 63;
    int b = wid >> 6, wy = (wid >> 3) & 7, wx = wid & 7;
    int h = wy * 8 + (n >> 3), w = wx * 8 + (n & 7);
    return (b << 12) + (h << 6) + w;
}

// pre-split a weight matrix into bf16 hi/lo (one uint4 = 8 outputs per thread)
__global__ void split_w_kernel(const float* __restrict__ w, uint4* __restrict__ hi,
                               uint4* __restrict__ lo) {
    int idx = blockIdx.x * 256 + threadIdx.x;     // uint4 index
    float4 v0 = *reinterpret_cast<const float4*>(w + (size_t)idx * 8);
    float4 v1 = *reinterpret_cast<const float4*>(w + (size_t)idx * 8 + 4);
    uint2 ph0, pl0, ph1, pl1;
    split_pack(v0, ph0, pl0);
    split_pack(v1, ph1, pl1);
    hi[idx] = make_uint4(ph0.x, ph0.y, ph1.x, ph1.y);
    lo[idx] = make_uint4(pl0.x, pl0.y, pl1.x, pl1.y);
}

// C = A @ W + bias, compensated bf16 (hh+hl+lh), fp32 accum.
// R4-proven shape: 128x64 tile, 4 acc frags/thread. A split in-kernel;
// B tile is a pure uint4 copy from pre-split weights.
template<int NCOLS, bool REMAP_IN, bool QKV_EPI>
__global__ void gemm_kernel(const float* __restrict__ A,
                            const bf16* __restrict__ Whi,
                            const bf16* __restrict__ Wlo,
                            const float* __restrict__ bias,
                            float* __restrict__ out)
{
    extern __shared__ __align__(16) char smraw[];
    bf16* smb = reinterpret_cast<bf16*>(smraw);
    // bf16-elem offsets: a_hi 0, a_lo 5120, b_hi 10240, b_lo 12544 (end 14848)

    const float* Asrc = REMAP_IN ? A : g_ao;

    int tid  = threadIdx.x;
    int warp = tid >> 5;
    int wm = warp >> 1, wn = warp & 1;
    int rbase = blockIdx.x * BM;
    int nbase = blockIdx.y * BN;

    wmma::fragment<wmma::accumulator, 16, 16, 16, float> acc[2][2];
    #pragma unroll
    for (int i = 0; i < 2; i++)
        #pragma unroll
        for (int j = 0; j < 2; j++) wmma::fill_fragment(acc[i][j], 0.0f);

    int brow = tid >> 3, bc4 = tid & 7;   // B copy coords: 32 rows x 8 uint4

    for (int kt = 0; kt < DIM / BK; kt++) {
        __syncthreads();
        // A tile: 128 rows x 32 cols f32 -> split to hi/lo (8 float4/row)
        #pragma unroll
        for (int s4 = 0; s4 < 4; s4++) {
            int idx = tid + s4 * 256;
            int i = idx >> 3, c = idx & 7;
            int r = rbase + i;
            int t = REMAP_IN ? win_token(r) : r;
            float4 v = *reinterpret_cast<const float4*>(
                Asrc + (size_t)t * DIM + kt * BK + c * 4);
            uint2 ph, pl; split_pack(v, ph, pl);
            *reinterpret_cast<uint2*>(smb + i * SA + c * 4)        = ph;
            *reinterpret_cast<uint2*>(smb + 5120 + i * SA + c * 4) = pl;
        }
        // B tile: pure uint4 copies from pre-split weights (hi + lo)
        {
            size_t goff = (size_t)(kt * BK + brow) * NCOLS + nbase + bc4 * 8;
            *reinterpret_cast<uint4*>(smb + 10240 + brow * SB + bc4 * 8) =
                *reinterpret_cast<const uint4*>(Whi + goff);
            *reinterpret_cast<uint4*>(smb + 12544 + brow * SB + bc4 * 8) =
                *reinterpret_cast<const uint4*>(Wlo + goff);
        }
        __syncthreads();
        #pragma unroll
        for (int ks = 0; ks < 2; ks++) {
            wmma::fragment<wmma::matrix_a, 16, 16, 16, bf16, wmma::row_major> fah[2], fal[2];
            wmma::fragment<wmma::matrix_b, 16, 16, 16, bf16, wmma::row_major> fbh[2], fbl[2];
            #pragma unroll
            for (int i = 0; i < 2; i++) {
                int row = wm * 32 + i * 16;
                wmma::load_matrix_sync(fah[i], smb + row * SA + ks * 16, SA);
                wmma::load_matrix_sync(fal[i], smb + 5120 + row * SA + ks * 16, SA);
            }
            #pragma unroll
            for (int j = 0; j < 2; j++) {
                int col = wn * 32 + j * 16;
                wmma::load_matrix_sync(fbh[j], smb + 10240 + (ks * 16) * SB + col, SB);
                wmma::load_matrix_sync(fbl[j], smb + 12544 + (ks * 16) * SB + col, SB);
            }
            #pragma unroll
            for (int i = 0; i < 2; i++)
                #pragma unroll
                for (int j = 0; j < 2; j++) {
                    wmma::mma_sync(acc[i][j], fah[i], fbh[j], acc[i][j]);
                    wmma::mma_sync(acc[i][j], fah[i], fbl[j], acc[i][j]);
                    wmma::mma_sync(acc[i][j], fal[i], fbh[j], acc[i][j]);
                }
        }
    }
    __syncthreads();
    float* csm = reinterpret_cast<float*>(smraw);
    #pragma unroll
    for (int i = 0; i < 2; i++)
        #pragma unroll
        for (int j = 0; j < 2; j++)
            wmma::store_matrix_sync(csm + (wm * 32 + i * 16) * SC + wn * 32 + j * 16,
                                    acc[i][j], SC, wmma::mem_row_major);
    __syncthreads();

    // Epilogue: 128x64 tile, 32 elems/thread (identical to R4)
    for (int s4 = 0; s4 < (BM * BN) / 256; s4++) {
        int idx = tid + s4 * 256;
        int i = idx >> 6, cl = idx & 63;
        int r = rbase + i;
        int c = nbase + cl;
        float v = csm[i * SC + cl] + bias[c];
        if (QKV_EPI) {
            int wid = r >> 6, n = r & 63;
            int which = c >> 9;           // 0=q 1=k 2=v
            int cc = c & 511;
            int head = cc >> 5, d = cc & 31;
            float o;
            if (which < 2) {
                // axial 2D RoPE: dims 0..15 rotate with row pos, 16..31 with col pos
                int j16 = d & 15;
                int g   = d >> 4;
                int pos = g ? (n & 7) : (n >> 3);
                int jj  = j16 & 7;
                float invf = exp2f(-1.6609640474436813f * (float)jj); // 10000^(-jj/8)
                float ang = (float)pos * invf;
                float sn, cs;
                sincosf(ang, &sn, &cs);
                int off = (j16 < 8) ? 8 : -8;
                float vp = csm[i * SC + cl + off] + bias[c + off];
                o = (j16 < 8) ? (v * cs - vp * sn) : (v * cs + vp * sn);
            } else {
                o = v;
            }
            float* dst = (which == 0) ? g_q : (which == 1) ? g_k : g_v;
            dst[(((size_t)wid * NH + head) * 64 + n) * HD + d] = o;
        } else {
            int t = win_token(r);
            out[(size_t)t * DIM + c] = v;
        }
    }
}

// One CTA per (window, head): S = (Q*scale) K^T, softmax, O = A V.
// Compensated bf16 MMA; f32 in/out globals. Softmax 4 threads/row (R6-proven).
__global__ void attn_kernel()
{
    extern __shared__ __align__(16) char smraw[];
    bf16* smb = reinterpret_cast<bf16*>(smraw);
    // bf16-elem offsets: qh 0, ql 2560, kh 5120, kl 7680, vh 10240, vl 12800
    float* s = reinterpret_cast<float*>(smraw + 30720);   // 64x68 f32
    bf16* ah = smb;                                        // overlay over q/k (dead after S)
    bf16* al = smb + 4608;

    int tid = threadIdx.x, warp = tid >> 5;
    int wid = blockIdx.x, head = blockIdx.y;
    size_t base = ((size_t)wid * NH + head) * (64 * HD);
    const float* qg = g_q + base;
    const float* kg = g_k + base;
    const float* vg = g_v + base;

    #pragma unroll
    for (int s4 = 0; s4 < 2; s4++) {
        int e = tid + s4 * 256;
        int n = e >> 3, d4 = e & 7;
        float4 v; uint2 ph, pl;
        v = *reinterpret_cast<const float4*>(qg + e * 4);
        v.x *= WSCALE; v.y *= WSCALE; v.z *= WSCALE; v.w *= WSCALE;
        split_pack(v, ph, pl);
        *reinterpret_cast<uint2*>(smb + n * SA + d4 * 4)        = ph;
        *reinterpret_cast<uint2*>(smb + 2560 + n * SA + d4 * 4) = pl;
        v = *reinterpret_cast<const float4*>(kg + e * 4);
        split_pack(v, ph, pl);
        *reinterpret_cast<uint2*>(smb + 5120 + n * SA + d4 * 4) = ph;
        *reinterpret_cast<uint2*>(smb + 7680 + n * SA + d4 * 4) = pl;
        v = *reinterpret_cast<const float4*>(vg + e * 4);
        split_pack(v, ph, pl);
        *reinterpret_cast<uint2*>(smb + 10240 + n * SA + d4 * 4) = ph;
        *reinterpret_cast<uint2*>(smb + 12800 + n * SA + d4 * 4) = pl;
    }
    __syncthreads();

    // S = Q K^T : 16 frags of 16x16, 2 per warp
    #pragma unroll
    for (int fi = 0; fi < 2; fi++) {
        int f = warp + fi * 8;
        int mi = f >> 2, ni = f & 3;
        wmma::fragment<wmma::accumulator, 16, 16, 16, float> acc;
        wmma::fill_fragment(acc, 0.0f);
        #pragma unroll
        for (int ks = 0; ks < 2; ks++) {
            wmma::fragment<wmma::matrix_a, 16, 16, 16, bf16, wmma::row_major> fah, fal;
            wmma::fragment<wmma::matrix_b, 16, 16, 16, bf16, wmma::col_major> fbh, fbl;
            wmma::load_matrix_sync(fah, smb + (mi * 16) * SA + ks * 16, SA);
            wmma::load_matrix_sync(fal, smb + 2560 + (mi * 16) * SA + ks * 16, SA);
            wmma::load_matrix_sync(fbh, smb + 5120 + (ni * 16) * SA + ks * 16, SA);
            wmma::load_matrix_sync(fbl, smb + 7680 + (ni * 16) * SA + ks * 16, SA);
            wmma::mma_sync(acc, fah, fbh, acc);
            wmma::mma_sync(acc, fah, fbl, acc);
            wmma::mma_sync(acc, fal, fbh, acc);
        }
        wmma::store_matrix_sync(s + (mi * 16) * SC + ni * 16, acc, SC, wmma::mem_row_major);
    }
    __syncthreads();

    // Row softmax: 4 threads per row (consecutive lanes), shfl reduce
    {
        int row = tid >> 2, l4 = tid & 3;
        float* sr = s + row * SC;
        float m = -1e30f;
        #pragma unroll
        for (int c = 0; c < 16; c++) m = fmaxf(m, sr[l4 * 16 + c]);
        m = fmaxf(m, __shfl_xor_sync(0xFFFFFFFF, m, 1));
        m = fmaxf(m, __shfl_xor_sync(0xFFFFFFFF, m, 2));
        float sum = 0.f;
        float e[16];
        #pragma unroll
        for (int c = 0; c < 16; c++) { e[c] = expf(sr[l4 * 16 + c] - m); sum += e[c]; }
        sum += __shfl_xor_sync(0xFFFFFFFF, sum, 1);
        sum += __shfl_xor_sync(0xFFFFFFFF, sum, 2);
        float inv = 1.f / sum;
        #pragma unroll
        for (int c = 0; c < 16; c++) {
            float a = e[c] * inv;
            bf16 h = __float2bfloat16(a);
            ah[row * SB + l4 * 16 + c] = h;
            al[row * SB + l4 * 16 + c] = __float2bfloat16(a - __bfloat162float(h));
        }
    }
    __syncthreads();

    // O = A V : 8 frags (4x2), one per warp; store f32 direct to g_ao
    {
        int mi = warp >> 1, ni = warp & 1;
        wmma::fragment<wmma::accumulator, 16, 16, 16, float> acc;
        wmma::fill_fragment(acc, 0.0f);
        #pragma unroll
        for (int ks = 0; ks < 4; ks++) {
            wmma::fragment<wmma::matrix_a, 16, 16, 16, bf16, wmma::row_major> fah, fal;
            wmma::fragment<wmma::matrix_b, 16, 16, 16, bf16, wmma::row_major> fbh, fbl;
            wmma::load_matrix_sync(fah, ah + (mi * 16) * SB + ks * 16, SB);
            wmma::load_matrix_sync(fal, al + (mi * 16) * SB + ks * 16, SB);
            wmma::load_matrix_sync(fbh, smb + 10240 + (ks * 16) * SA + ni * 16, SA);
            wmma::load_matrix_sync(fbl, smb + 12800 + (ks * 16) * SA + ni * 16, SA);
            wmma::mma_sync(acc, fah, fbh, acc);
            wmma::mma_sync(acc, fah, fbl, acc);
            wmma::mma_sync(acc, fal, fbh, acc);
        }
        wmma::store_matrix_sync(
            g_ao + (size_t)(wid * 64 + mi * 16) * DIM + head * HD + ni * 16,
            acc, DIM, wmma::mem_row_major);
    }
}

extern "C" void kernel_launch(void* const* d_in, const int* in_sizes, int n_in,
                              void* d_out, int out_size)
{
    (void)in_sizes; (void)n_in; (void)out_size;
    const float* x      = (const float*)d_in[0];
    const float* qkv_w  = (const float*)d_in[1];
    const float* qkv_b  = (const float*)d_in[2];
    // d_in[3], d_in[4] (kv_w, kv_b) are dead code in the reference output
    const float* proj_w = (const float*)d_in[5];
    const float* proj_b = (const float*)d_in[6];
    float* out = (float*)d_out;

    const int gemm_smem = BM * SC * 4;            // 34816 B (tiles need 29696)
    const int attn_smem = 30720 + 64 * SC * 4;    // 48128 B (< 48KB default limit)

    split_w_kernel<<<DIM * NQKV / 8 / 256, 256>>>(qkv_w, g_wqh, g_wql);
    split_w_kernel<<<DIM * DIM / 8 / 256, 256>>>(proj_w, g_wph, g_wpl);

    gemm_kernel<NQKV, true, true>
        <<<dim3(NTOK / BM, NQKV / BN), 256, gemm_smem>>>(
            x, (const bf16*)g_wqh, (const bf16*)g_wql, qkv_b, nullptr);
    attn_kernel<<<dim3(NWIN, NH), 256, attn_smem>>>();
    gemm_kernel<DIM, false, false>
        <<<dim3(NTOK / BM, DIM / BN), 256, gemm_smem>>>(
            nullptr, (const bf16*)g_wph, (const bf16*)g_wpl, proj_b, out);
}

// round 8
// speedup vs baseline: 5.6685x; 2.7573x over previous
#include <cuda_runtime.h>
#include <cuda_bf16.h>
#include <mma.h>
#include <cstdint>

using namespace nvcuda;
typedef __nv_bfloat16 bf16;

#define DIM    512
#define NH     16
#define HD     32
#define NWIN   512      // 8 batches * 8*8 windows
#define NTOK   32768    // 512 windows * 64 tokens
#define NQKV   1536
#define WSCALE 0.17677669529663687f   // 32^-0.5

// GEMM tiling (R4-proven shape)
#define BM 128
#define BN 64
#define BK 32
#define SA 40   // A smem row stride (bf16 elems)
#define SB 72   // B smem row stride (bf16 elems)
#define SC 68   // C epilogue stride (f32)

// Scratch (__device__ globals). RULE: only referenced from DEVICE code —
// never passed as kernel arguments from host (host shadow + ATS trap).
__device__ float g_q[(size_t)NWIN * NH * 64 * HD];
__device__ float g_k[(size_t)NWIN * NH * 64 * HD];
__device__ float g_v[(size_t)NWIN * NH * 64 * HD];
__device__ float g_ao[(size_t)NTOK * DIM];
// pre-split A (x, windowed row order) and weights, bf16 hi/lo packed as uint4
__device__ uint4 g_xhi[(size_t)NTOK * DIM / 8];
__device__ uint4 g_xlo[(size_t)NTOK * DIM / 8];
__device__ uint4 g_wqh[(size_t)DIM * NQKV / 8];
__device__ uint4 g_wql[(size_t)DIM * NQKV / 8];
__device__ uint4 g_wph[(size_t)DIM * DIM / 8];
__device__ uint4 g_wpl[(size_t)DIM * DIM / 8];

__device__ __forceinline__ unsigned short us(bf16 v) { return __bfloat16_as_ushort(v); }

// split float4 -> packed bf16 hi pair-of-uint / lo pair-of-uint
__device__ __forceinline__ void split_pack(float4 v, uint2& ph, uint2& pl) {
    bf16 h0 = __float2bfloat16(v.x), h1 = __float2bfloat16(v.y);
    bf16 h2 = __float2bfloat16(v.z), h3 = __float2bfloat16(v.w);
    bf16 l0 = __float2bfloat16(v.x - __bfloat162float(h0));
    bf16 l1 = __float2bfloat16(v.y - __bfloat162float(h1));
    bf16 l2 = __float2bfloat16(v.z - __bfloat162float(h2));
    bf16 l3 = __float2bfloat16(v.w - __bfloat162float(h3));
    ph.x = us(h0) | ((unsigned)us(h1) << 16);
    ph.y = us(h2) | ((unsigned)us(h3) << 16);
    pl.x = us(l0) | ((unsigned)us(l1) << 16);
    pl.y = us(l2) | ((unsigned)us(l3) << 16);
}

// windowed row index -> global token index
__device__ __forceinline__ int win_token(int r) {
    int wid = r >> 6, n = r & 63;
    int b = wid >> 6, wy = (wid >> 3) & 7, wx = wid & 7;
    int h = wy * 8 + (n >> 3), w = wx * 8 + (n & 7);
    return (b << 12) + (h << 6) + w;
}

// split x into bf16 hi/lo uint4 in WINDOWED row order (device-code global refs)
__global__ void split_x_kernel(const float* __restrict__ x) {
    int idx = blockIdx.x * 256 + threadIdx.x;   // uint4 index (8 floats)
    int r = idx >> 6, c8 = idx & 63;            // DIM/8 = 64 uint4 per row
    int t = win_token(r);
    const float* src = x + (size_t)t * DIM + c8 * 8;
    float4 v0 = *reinterpret_cast<const float4*>(src);
    float4 v1 = *reinterpret_cast<const float4*>(src + 4);
    uint2 ph0, pl0, ph1, pl1;
    split_pack(v0, ph0, pl0);
    split_pack(v1, ph1, pl1);
    g_xhi[idx] = make_uint4(ph0.x, ph0.y, ph1.x, ph1.y);
    g_xlo[idx] = make_uint4(pl0.x, pl0.y, pl1.x, pl1.y);
}

// pre-split a weight matrix (which: 0=qkv_w, 1=proj_w); dst chosen in device code
__global__ void split_w_kernel(const float* __restrict__ w, int which) {
    int idx = blockIdx.x * 256 + threadIdx.x;   // uint4 index
    float4 v0 = *reinterpret_cast<const float4*>(w + (size_t)idx * 8);
    float4 v1 = *reinterpret_cast<const float4*>(w + (size_t)idx * 8 + 4);
    uint2 ph0, pl0, ph1, pl1;
    split_pack(v0, ph0, pl0);
    split_pack(v1, pl1.x == 0 ? ph1 : ph1, pl1);   // (no-op guard removed below)
    split_pack(v1, ph1, pl1);
    uint4* hi = which ? g_wph : g_wqh;
    uint4* lo = which ? g_wpl : g_wql;
    hi[idx] = make_uint4(ph0.x, ph0.y, ph1.x, ph1.y);
    lo[idx] = make_uint4(pl0.x, pl0.y, pl1.x, pl1.y);
}

// C = A @ W + bias, compensated bf16 (hh+hl+lh), fp32 accum. R4-proven 128x64 tile.
// QKV: A from pre-split g_xhi/g_xlo (pure uint4 copies), W from g_wqh/g_wql.
// proj: A from g_ao (f32, split in-kernel), W from g_wph/g_wpl.
template<bool QKV>
__global__ void gemm_kernel(const float* __restrict__ bias, float* __restrict__ out)
{
    constexpr int NCOLS = QKV ? NQKV : DIM;
    extern __shared__ __align__(16) char smraw[];
    bf16* smb = reinterpret_cast<bf16*>(smraw);
    // bf16-elem offsets: a_hi 0, a_lo 5120, b_hi 10240, b_lo 12544 (end 14848)

    int tid  = threadIdx.x;
    int warp = tid >> 5;
    int wm = warp >> 1, wn = warp & 1;
    int rbase = blockIdx.x * BM;
    int nbase = blockIdx.y * BN;

    wmma::fragment<wmma::accumulator, 16, 16, 16, float> acc[2][2];
    #pragma unroll
    for (int i = 0; i < 2; i++)
        #pragma unroll
        for (int j = 0; j < 2; j++) wmma::fill_fragment(acc[i][j], 0.0f);

    int brow = tid >> 3, bc4 = tid & 7;   // B copy coords: 32 rows x 8 uint4
    const uint4* wh = QKV ? g_wqh : g_wph;   // device-code refs: real device addrs
    const uint4* wl = QKV ? g_wql : g_wpl;

    for (int kt = 0; kt < DIM / BK; kt++) {
        __syncthreads();
        if (QKV) {
            // A tile: pure uint4 copies from pre-split x (windowed rows)
            #pragma unroll
            for (int s4 = 0; s4 < 2; s4++) {
                int idx = tid + s4 * 256;          // 0..511
                int i = idx >> 2, c = idx & 3;     // row, uint4-col (4 per row)
                size_t go = (size_t)(rbase + i) * (DIM / 8) + kt * 4 + c;
                *reinterpret_cast<uint4*>(smb + i * SA + c * 8)        = g_xhi[go];
                *reinterpret_cast<uint4*>(smb + 5120 + i * SA + c * 8) = g_xlo[go];
            }
        } else {
            // A tile: f32 from g_ao, split in-kernel (rows are windowed order)
            #pragma unroll
            for (int s4 = 0; s4 < 4; s4++) {
                int idx = tid + s4 * 256;
                int i = idx >> 3, c = idx & 7;
                float4 v = *reinterpret_cast<const float4*>(
                    g_ao + (size_t)(rbase + i) * DIM + kt * BK + c * 4);
                uint2 ph, pl; split_pack(v, ph, pl);
                *reinterpret_cast<uint2*>(smb + i * SA + c * 4)        = ph;
                *reinterpret_cast<uint2*>(smb + 5120 + i * SA + c * 4) = pl;
            }
        }
        // B tile: pure uint4 copies from pre-split weights
        {
            size_t go = ((size_t)(kt * BK + brow) * NCOLS + nbase) / 8 + bc4;
            *reinterpret_cast<uint4*>(smb + 10240 + brow * SB + bc4 * 8) = wh[go];
            *reinterpret_cast<uint4*>(smb + 12544 + brow * SB + bc4 * 8) = wl[go];
        }
        __syncthreads();
        #pragma unroll
        for (int ks = 0; ks < 2; ks++) {
            wmma::fragment<wmma::matrix_a, 16, 16, 16, bf16, wmma::row_major> fah[2], fal[2];
            wmma::fragment<wmma::matrix_b, 16, 16, 16, bf16, wmma::row_major> fbh[2], fbl[2];
            #pragma unroll
            for (int i = 0; i < 2; i++) {
                int row = wm * 32 + i * 16;
                wmma::load_matrix_sync(fah[i], smb + row * SA + ks * 16, SA);
                wmma::load_matrix_sync(fal[i], smb + 5120 + row * SA + ks * 16, SA);
            }
            #pragma unroll
            for (int j = 0; j < 2; j++) {
                int col = wn * 32 + j * 16;
                wmma::load_matrix_sync(fbh[j], smb + 10240 + (ks * 16) * SB + col, SB);
                wmma::load_matrix_sync(fbl[j], smb + 12544 + (ks * 16) * SB + col, SB);
            }
            #pragma unroll
            for (int i = 0; i < 2; i++)
                #pragma unroll
                for (int j = 0; j < 2; j++) {
                    wmma::mma_sync(acc[i][j], fah[i], fbh[j], acc[i][j]);
                    wmma::mma_sync(acc[i][j], fah[i], fbl[j], acc[i][j]);
                    wmma::mma_sync(acc[i][j], fal[i], fbh[j], acc[i][j]);
                }
        }
    }
    __syncthreads();
    float* csm = reinterpret_cast<float*>(smraw);
    #pragma unroll
    for (int i = 0; i < 2; i++)
        #pragma unroll
        for (int j = 0; j < 2; j++)
            wmma::store_matrix_sync(csm + (wm * 32 + i * 16) * SC + wn * 32 + j * 16,
                                    acc[i][j], SC, wmma::mem_row_major);
    __syncthreads();

    // Epilogue: 128x64 tile, 32 elems/thread (identical to R4)
    for (int s4 = 0; s4 < (BM * BN) / 256; s4++) {
        int idx = tid + s4 * 256;
        int i = idx >> 6, cl = idx & 63;
        int r = rbase + i;
        int c = nbase + cl;
        float v = csm[i * SC + cl] + bias[c];
        if (QKV) {
            int wid = r >> 6, n = r & 63;
            int which = c >> 9;           // 0=q 1=k 2=v
            int cc = c & 511;
            int head = cc >> 5, d = cc & 31;
            float o;
            if (which < 2) {
                // axial 2D RoPE: dims 0..15 rotate with row pos, 16..31 with col pos
                int j16 = d & 15;
                int g   = d >> 4;
                int pos = g ? (n & 7) : (n >> 3);
                int jj  = j16 & 7;
                float invf = exp2f(-1.6609640474436813f * (float)jj); // 10000^(-jj/8)
                float ang = (float)pos * invf;
                float sn, cs;
                sincosf(ang, &sn, &cs);
                int off = (j16 < 8) ? 8 : -8;
                float vp = csm[i * SC + cl + off] + bias[c + off];
                o = (j16 < 8) ? (v * cs - vp * sn) : (v * cs + vp * sn);
            } else {
                o = v;
            }
            float* dst = (which == 0) ? g_q : (which == 1) ? g_k : g_v;
            dst[(((size_t)wid * NH + head) * 64 + n) * HD + d] = o;
        } else {
            int t = win_token(r);
            out[(size_t)t * DIM + c] = v;
        }
    }
}

// One CTA per (window, head): S = (Q*scale) K^T, softmax, O = A V.
// Compensated bf16 MMA; f32 in/out via device-code global refs (proven R6/R7, 105us).
__global__ void attn_kernel()
{
    extern __shared__ __align__(16) char smraw[];
    bf16* smb = reinterpret_cast<bf16*>(smraw);
    // bf16-elem offsets: qh 0, ql 2560, kh 5120, kl 7680, vh 10240, vl 12800
    float* s = reinterpret_cast<float*>(smraw + 30720);   // 64x68 f32
    bf16* ah = smb;                                        // overlay over q/k (dead after S)
    bf16* al = smb + 4608;

    int tid = threadIdx.x, warp = tid >> 5;
    int wid = blockIdx.x, head = blockIdx.y;
    size_t base = ((size_t)wid * NH + head) * (64 * HD);
    const float* qg = g_q + base;
    const float* kg = g_k + base;
    const float* vg = g_v + base;

    #pragma unroll
    for (int s4 = 0; s4 < 2; s4++) {
        int e = tid + s4 * 256;
        int n = e >> 3, d4 = e & 7;
        float4 v; uint2 ph, pl;
        v = *reinterpret_cast<const float4*>(qg + e * 4);
        v.x *= WSCALE; v.y *= WSCALE; v.z *= WSCALE; v.w *= WSCALE;
        split_pack(v, ph, pl);
        *reinterpret_cast<uint2*>(smb + n * SA + d4 * 4)        = ph;
        *reinterpret_cast<uint2*>(smb + 2560 + n * SA + d4 * 4) = pl;
        v = *reinterpret_cast<const float4*>(kg + e * 4);
        split_pack(v, ph, pl);
        *reinterpret_cast<uint2*>(smb + 5120 + n * SA + d4 * 4) = ph;
        *reinterpret_cast<uint2*>(smb + 7680 + n * SA + d4 * 4) = pl;
        v = *reinterpret_cast<const float4*>(vg + e * 4);
        split_pack(v, ph, pl);
        *reinterpret_cast<uint2*>(smb + 10240 + n * SA + d4 * 4) = ph;
        *reinterpret_cast<uint2*>(smb + 12800 + n * SA + d4 * 4) = pl;
    }
    __syncthreads();

    // S = Q K^T : 16 frags of 16x16, 2 per warp
    #pragma unroll
    for (int fi = 0; fi < 2; fi++) {
        int f = warp + fi * 8;
        int mi = f >> 2, ni = f & 3;
        wmma::fragment<wmma::accumulator, 16, 16, 16, float> acc;
        wmma::fill_fragment(acc, 0.0f);
        #pragma unroll
        for (int ks = 0; ks < 2; ks++) {
            wmma::fragment<wmma::matrix_a, 16, 16, 16, bf16, wmma::row_major> fah, fal;
            wmma::fragment<wmma::matrix_b, 16, 16, 16, bf16, wmma::col_major> fbh, fbl;
            wmma::load_matrix_sync(fah, smb + (mi * 16) * SA + ks * 16, SA);
            wmma::load_matrix_sync(fal, smb + 2560 + (mi * 16) * SA + ks * 16, SA);
            wmma::load_matrix_sync(fbh, smb + 5120 + (ni * 16) * SA + ks * 16, SA);
            wmma::load_matrix_sync(fbl, smb + 7680 + (ni * 16) * SA + ks * 16, SA);
            wmma::mma_sync(acc, fah, fbh, acc);
            wmma::mma_sync(acc, fah, fbl, acc);
            wmma::mma_sync(acc, fal, fbh, acc);
        }
        wmma::store_matrix_sync(s + (mi * 16) * SC + ni * 16, acc, SC, wmma::mem_row_major);
    }
    __syncthreads();

    // Row softmax: 4 threads per row (consecutive lanes), shfl reduce
    {
        int row = tid >> 2, l4 = tid & 3;
        float* sr = s + row * SC;
        float m = -1e30f;
        #pragma unroll
        for (int c = 0; c < 16; c++) m = fmaxf(m, sr[l4 * 16 + c]);
        m = fmaxf(m, __shfl_xor_sync(0xFFFFFFFF, m, 1));
        m = fmaxf(m, __shfl_xor_sync(0xFFFFFFFF, m, 2));
        float sum = 0.f;
        float e[16];
        #pragma unroll
        for (int c = 0; c < 16; c++) { e[c] = expf(sr[l4 * 16 + c] - m); sum += e[c]; }
        sum += __shfl_xor_sync(0xFFFFFFFF, sum, 1);
        sum += __shfl_xor_sync(0xFFFFFFFF, sum, 2);
        float inv = 1.f / sum;
        #pragma unroll
        for (int c = 0; c < 16; c++) {
            float a = e[c] * inv;
            bf16 h = __float2bfloat16(a);
            ah[row * SB + l4 * 16 + c] = h;
            al[row * SB + l4 * 16 + c] = __float2bfloat16(a - __bfloat162float(h));
        }
    }
    __syncthreads();

    // O = A V : 8 frags (4x2), one per warp; store f32 direct to g_ao
    {
        int mi = warp >> 1, ni = warp & 1;
        wmma::fragment<wmma::accumulator, 16, 16, 16, float> acc;
        wmma::fill_fragment(acc, 0.0f);
        #pragma unroll
        for (int ks = 0; ks < 4; ks++) {
            wmma::fragment<wmma::matrix_a, 16, 16, 16, bf16, wmma::row_major> fah, fal;
            wmma::fragment<wmma::matrix_b, 16, 16, 16, bf16, wmma::row_major> fbh, fbl;
            wmma::load_matrix_sync(fah, ah + (mi * 16) * SB + ks * 16, SB);
            wmma::load_matrix_sync(fal, al + (mi * 16) * SB + ks * 16, SB);
            wmma::load_matrix_sync(fbh, smb + 10240 + (ks * 16) * SA + ni * 16, SA);
            wmma::load_matrix_sync(fbl, smb + 12800 + (ks * 16) * SA + ni * 16, SA);
            wmma::mma_sync(acc, fah, fbh, acc);
            wmma::mma_sync(acc, fah, fbl, acc);
            wmma::mma_sync(acc, fal, fbh, acc);
        }
        wmma::store_matrix_sync(
            g_ao + (size_t)(wid * 64 + mi * 16) * DIM + head * HD + ni * 16,
            acc, DIM, wmma::mem_row_major);
    }
}

extern "C" void kernel_launch(void* const* d_in, const int* in_sizes, int n_in,
                              void* d_out, int out_size)
{
    (void)in_sizes; (void)n_in; (void)out_size;
    const float* x      = (const float*)d_in[0];
    const float* qkv_w  = (const float*)d_in[1];
    const float* qkv_b  = (const float*)d_in[2];
    // d_in[3], d_in[4] (kv_w, kv_b) are dead code in the reference output
    const float* proj_w = (const float*)d_in[5];
    const float* proj_b = (const float*)d_in[6];
    float* out = (float*)d_out;

    const int gemm_smem = BM * SC * 4;            // 34816 B (tiles need 29696)
    const int attn_smem = 30720 + 64 * SC * 4;    // 48128 B (< 48KB default limit)

    split_x_kernel<<<NTOK * DIM / 8 / 256, 256>>>(x);
    split_w_kernel<<<DIM * NQKV / 8 / 256, 256>>>(qkv_w, 0);
    split_w_kernel<<<DIM * DIM  / 8 / 256, 256>>>(proj_w, 1);

    gemm_kernel<true>
        <<<dim3(NTOK / BM, NQKV / BN), 256, gemm_smem>>>(qkv_b, nullptr);
    attn_kernel<<<dim3(NWIN, NH), 256, attn_smem>>>();
    gemm_kernel<false>
        <<<dim3(NTOK / BM, DIM / BN), 256, gemm_smem>>>(proj_b, out);
}

// round 9
// speedup vs baseline: 6.1694x; 1.0884x over previous
#include <cuda_runtime.h>
#include <cuda_bf16.h>
#include <mma.h>
#include <cstdint>

using namespace nvcuda;
typedef __nv_bfloat16 bf16;

#define DIM    512
#define NH     16
#define HD     32
#define NWIN   512      // 8 batches * 8*8 windows
#define NTOK   32768    // 512 windows * 64 tokens
#define NQKV   1536
#define WSCALE 0.17677669529663687f   // 32^-0.5

// GEMM tiling (128x64 tile, 4 acc frags/thread — R4-proven)
#define BM 128
#define BN 64
#define BK 32
#define SA 40    // A smem row stride (bf16)
#define SB 72    // B smem row stride (bf16)
#define SC 68    // C epilogue stride (f32)
#define STAGE_B 29696          // bytes per smem stage
#define STAGE_E 14848          // bf16 elems per stage

// Scratch (__device__ globals). RULE: referenced ONLY from device code.
__device__ float g_q[(size_t)NWIN * NH * 64 * HD];
__device__ float g_k[(size_t)NWIN * NH * 64 * HD];
__device__ float g_v[(size_t)NWIN * NH * 64 * HD];
// pre-split operands, bf16 hi/lo packed as uint4
__device__ uint4 g_xhi[(size_t)NTOK * DIM / 8];
__device__ uint4 g_xlo[(size_t)NTOK * DIM / 8];
__device__ uint4 g_aoh[(size_t)NTOK * DIM / 8];   // attention out hi
__device__ uint4 g_aol[(size_t)NTOK * DIM / 8];   // attention out lo
__device__ uint4 g_wqh[(size_t)DIM * NQKV / 8];
__device__ uint4 g_wql[(size_t)DIM * NQKV / 8];
__device__ uint4 g_wph[(size_t)DIM * DIM / 8];
__device__ uint4 g_wpl[(size_t)DIM * DIM / 8];

__device__ __forceinline__ unsigned short us(bf16 v) { return __bfloat16_as_ushort(v); }

__device__ __forceinline__ void split_pack(float4 v, uint2& ph, uint2& pl) {
    bf16 h0 = __float2bfloat16(v.x), h1 = __float2bfloat16(v.y);
    bf16 h2 = __float2bfloat16(v.z), h3 = __float2bfloat16(v.w);
    bf16 l0 = __float2bfloat16(v.x - __bfloat162float(h0));
    bf16 l1 = __float2bfloat16(v.y - __bfloat162float(h1));
    bf16 l2 = __float2bfloat16(v.z - __bfloat162float(h2));
    bf16 l3 = __float2bfloat16(v.w - __bfloat162float(h3));
    ph.x = us(h0) | ((unsigned)us(h1) << 16);
    ph.y = us(h2) | ((unsigned)us(h3) << 16);
    pl.x = us(l0) | ((unsigned)us(l1) << 16);
    pl.y = us(l2) | ((unsigned)us(l3) << 16);
}

__device__ __forceinline__ int win_token(int r) {
    int wid = r >> 6, n = r & 63;
    int b = wid >> 6, wy = (wid >> 3) & 7, wx = wid & 7;
    int h = wy * 8 + (n >> 3), w = wx * 8 + (n & 7);
    return (b << 12) + (h << 6) + w;
}

__device__ __forceinline__ uint32_t smem_u32(const void* p) {
    uint32_t a;
    asm("{ .reg .u64 t; cvta.to.shared.u64 t, %1; cvt.u32.u64 %0, t; }" : "=r"(a) : "l"(p));
    return a;
}
#define CP_ASYNC16(dst, src) \
    asm volatile("cp.async.cg.shared.global [%0], [%1], 16;" :: "r"(dst), "l"(src))
#define CP_COMMIT()  asm volatile("cp.async.commit_group;" ::: "memory")
#define CP_WAIT(n)   asm volatile("cp.async.wait_group %0;" :: "n"(n) : "memory")

// split x -> bf16 hi/lo uint4 in WINDOWED row order
__global__ void split_x_kernel(const float* __restrict__ x) {
    int idx = blockIdx.x * 256 + threadIdx.x;   // uint4 index (8 floats)
    int r = idx >> 6, c8 = idx & 63;
    int t = win_token(r);
    const float* src = x + (size_t)t * DIM + c8 * 8;
    float4 v0 = *reinterpret_cast<const float4*>(src);
    float4 v1 = *reinterpret_cast<const float4*>(src + 4);
    uint2 ph0, pl0, ph1, pl1;
    split_pack(v0, ph0, pl0);
    split_pack(v1, ph1, pl1);
    g_xhi[idx] = make_uint4(ph0.x, ph0.y, ph1.x, ph1.y);
    g_xlo[idx] = make_uint4(pl0.x, pl0.y, pl1.x, pl1.y);
}

// pre-split a weight matrix (which: 0=qkv_w, 1=proj_w)
__global__ void split_w_kernel(const float* __restrict__ w, int which) {
    int idx = blockIdx.x * 256 + threadIdx.x;
    float4 v0 = *reinterpret_cast<const float4*>(w + (size_t)idx * 8);
    float4 v1 = *reinterpret_cast<const float4*>(w + (size_t)idx * 8 + 4);
    uint2 ph0, pl0, ph1, pl1;
    split_pack(v0, ph0, pl0);
    split_pack(v1, ph1, pl1);
    uint4* hi = which ? g_wph : g_wqh;
    uint4* lo = which ? g_wpl : g_wql;
    hi[idx] = make_uint4(ph0.x, ph0.y, ph1.x, ph1.y);
    lo[idx] = make_uint4(pl0.x, pl0.y, pl1.x, pl1.y);
}

// C = A @ W + bias, compensated bf16 (hh+hl+lh), fp32 accum.
// Double-buffered smem, all tile loads via cp.async (pure 16B copies).
template<bool QKV>
__global__ void gemm_kernel(const float* __restrict__ bias, float* __restrict__ out)
{
    constexpr int NCOLS = QKV ? NQKV : DIM;
    extern __shared__ __align__(16) char smraw[];
    bf16* smb0 = reinterpret_cast<bf16*>(smraw);
    const uint32_t sm_addr = smem_u32(smraw);

    int tid  = threadIdx.x;
    int warp = tid >> 5;
    int wm = warp >> 1, wn = warp & 1;
    int rbase = blockIdx.x * BM;
    int nbase = blockIdx.y * BN;

    const uint4* ah = QKV ? g_xhi : g_aoh;   // device-code refs (real device addrs)
    const uint4* al = QKV ? g_xlo : g_aol;
    const uint4* wh = QKV ? g_wqh : g_wph;
    const uint4* wl = QKV ? g_wql : g_wpl;

    wmma::fragment<wmma::accumulator, 16, 16, 16, float> acc[2][2];
    #pragma unroll
    for (int i = 0; i < 2; i++)
        #pragma unroll
        for (int j = 0; j < 2; j++) wmma::fill_fragment(acc[i][j], 0.0f);

    // per-thread copy coords
    int ai0 = tid >> 2,          ac = tid & 3;           // A: idx=tid
    int ai1 = (tid + 256) >> 2;                          // A: idx=tid+256
    int brow = tid >> 3,         bc4 = tid & 7;          // B

    auto issue = [&](int kt) {
        uint32_t st = sm_addr + (kt & 1) * STAGE_B;
        size_t ga0 = (size_t)(rbase + ai0) * (DIM / 8) + kt * 4 + ac;
        size_t ga1 = (size_t)(rbase + ai1) * (DIM / 8) + kt * 4 + ac;
        CP_ASYNC16(st + ai0 * 80 + ac * 16,          ah + ga0);
        CP_ASYNC16(st + ai1 * 80 + ac * 16,          ah + ga1);
        CP_ASYNC16(st + 10240 + ai0 * 80 + ac * 16,  al + ga0);
        CP_ASYNC16(st + 10240 + ai1 * 80 + ac * 16,  al + ga1);
        size_t gb = ((size_t)(kt * BK + brow) * NCOLS + nbase) / 8 + bc4;
        CP_ASYNC16(st + 20480 + brow * 144 + bc4 * 16, wh + gb);
        CP_ASYNC16(st + 25088 + brow * 144 + bc4 * 16, wl + gb);
        CP_COMMIT();
    };

    issue(0);

    const int NKT = DIM / BK;   // 16
    for (int kt = 0; kt < NKT; kt++) {
        __syncthreads();                 // all warps done computing stage (kt-1)
        if (kt + 1 < NKT) { issue(kt + 1); CP_WAIT(1); }
        else              { CP_WAIT(0); }
        __syncthreads();                 // stage kt visible to all warps

        bf16* smb = smb0 + (kt & 1) * STAGE_E;
        #pragma unroll
        for (int ks = 0; ks < 2; ks++) {
            wmma::fragment<wmma::matrix_a, 16, 16, 16, bf16, wmma::row_major> fah[2], fal[2];
            wmma::fragment<wmma::matrix_b, 16, 16, 16, bf16, wmma::row_major> fbh[2], fbl[2];
            #pragma unroll
            for (int i = 0; i < 2; i++) {
                int row = wm * 32 + i * 16;
                wmma::load_matrix_sync(fah[i], smb + row * SA + ks * 16, SA);
                wmma::load_matrix_sync(fal[i], smb + 5120 + row * SA + ks * 16, SA);
            }
            #pragma unroll
            for (int j = 0; j < 2; j++) {
                int col = wn * 32 + j * 16;
                wmma::load_matrix_sync(fbh[j], smb + 10240 + (ks * 16) * SB + col, SB);
                wmma::load_matrix_sync(fbl[j], smb + 12544 + (ks * 16) * SB + col, SB);
            }
            #pragma unroll
            for (int i = 0; i < 2; i++)
                #pragma unroll
                for (int j = 0; j < 2; j++) {
                    wmma::mma_sync(acc[i][j], fah[i], fbh[j], acc[i][j]);
                    wmma::mma_sync(acc[i][j], fah[i], fbl[j], acc[i][j]);
                    wmma::mma_sync(acc[i][j], fal[i], fbh[j], acc[i][j]);
                }
        }
    }
    __syncthreads();
    float* csm = reinterpret_cast<float*>(smraw);
    #pragma unroll
    for (int i = 0; i < 2; i++)
        #pragma unroll
        for (int j = 0; j < 2; j++)
            wmma::store_matrix_sync(csm + (wm * 32 + i * 16) * SC + wn * 32 + j * 16,
                                    acc[i][j], SC, wmma::mem_row_major);
    __syncthreads();

    // Epilogue: 128x64 tile, 32 elems/thread
    for (int s4 = 0; s4 < (BM * BN) / 256; s4++) {
        int idx = tid + s4 * 256;
        int i = idx >> 6, cl = idx & 63;
        int r = rbase + i;
        int c = nbase + cl;
        float v = csm[i * SC + cl] + bias[c];
        if (QKV) {
            int wid = r >> 6, n = r & 63;
            int which = c >> 9;           // 0=q 1=k 2=v
            int cc = c & 511;
            int head = cc >> 5, d = cc & 31;
            float o;
            if (which < 2) {
                int j16 = d & 15;
                int g   = d >> 4;
                int pos = g ? (n & 7) : (n >> 3);
                int jj  = j16 & 7;
                float invf = exp2f(-1.6609640474436813f * (float)jj); // 10000^(-jj/8)
                float ang = (float)pos * invf;
                float sn, cs;
                sincosf(ang, &sn, &cs);
                int off = (j16 < 8) ? 8 : -8;
                float vp = csm[i * SC + cl + off] + bias[c + off];
                o = (j16 < 8) ? (v * cs - vp * sn) : (v * cs + vp * sn);
            } else {
                o = v;
            }
            float* dst = (which == 0) ? g_q : (which == 1) ? g_k : g_v;
            dst[(((size_t)wid * NH + head) * 64 + n) * HD + d] = o;
        } else {
            int t = win_token(r);
            out[(size_t)t * DIM + c] = v;
        }
    }
}

// One CTA per (window, head): S = (Q*scale) K^T, softmax, O = A V.
// Output written pre-split (bf16 hi/lo) for the proj GEMM's cp.async path.
__global__ void attn_kernel()
{
    extern __shared__ __align__(16) char smraw[];
    bf16* smb = reinterpret_cast<bf16*>(smraw);
    // bf16-elem offsets: qh 0, ql 2560, kh 5120, kl 7680, vh 10240, vl 12800
    float* s = reinterpret_cast<float*>(smraw + 30720);   // 64x68 f32
    bf16* ah = smb;                                        // overlay (dead after S)
    bf16* al = smb + 4608;

    int tid = threadIdx.x, warp = tid >> 5;
    int wid = blockIdx.x, head = blockIdx.y;
    size_t base = ((size_t)wid * NH + head) * (64 * HD);
    const float* qg = g_q + base;
    const float* kg = g_k + base;
    const float* vg = g_v + base;

    #pragma unroll
    for (int s4 = 0; s4 < 2; s4++) {
        int e = tid + s4 * 256;
        int n = e >> 3, d4 = e & 7;
        float4 v; uint2 ph, pl;
        v = *reinterpret_cast<const float4*>(qg + e * 4);
        v.x *= WSCALE; v.y *= WSCALE; v.z *= WSCALE; v.w *= WSCALE;
        split_pack(v, ph, pl);
        *reinterpret_cast<uint2*>(smb + n * SA + d4 * 4)        = ph;
        *reinterpret_cast<uint2*>(smb + 2560 + n * SA + d4 * 4) = pl;
        v = *reinterpret_cast<const float4*>(kg + e * 4);
        split_pack(v, ph, pl);
        *reinterpret_cast<uint2*>(smb + 5120 + n * SA + d4 * 4) = ph;
        *reinterpret_cast<uint2*>(smb + 7680 + n * SA + d4 * 4) = pl;
        v = *reinterpret_cast<const float4*>(vg + e * 4);
        split_pack(v, ph, pl);
        *reinterpret_cast<uint2*>(smb + 10240 + n * SA + d4 * 4) = ph;
        *reinterpret_cast<uint2*>(smb + 12800 + n * SA + d4 * 4) = pl;
    }
    __syncthreads();

    // S = Q K^T : 16 frags of 16x16, 2 per warp
    #pragma unroll
    for (int fi = 0; fi < 2; fi++) {
        int f = warp + fi * 8;
        int mi = f >> 2, ni = f & 3;
        wmma::fragment<wmma::accumulator, 16, 16, 16, float> acc;
        wmma::fill_fragment(acc, 0.0f);
        #pragma unroll
        for (int ks = 0; ks < 2; ks++) {
            wmma::fragment<wmma::matrix_a, 16, 16, 16, bf16, wmma::row_major> fah, fal;
            wmma::fragment<wmma::matrix_b, 16, 16, 16, bf16, wmma::col_major> fbh, fbl;
            wmma::load_matrix_sync(fah, smb + (mi * 16) * SA + ks * 16, SA);
            wmma::load_matrix_sync(fal, smb + 2560 + (mi * 16) * SA + ks * 16, SA);
            wmma::load_matrix_sync(fbh, smb + 5120 + (ni * 16) * SA + ks * 16, SA);
            wmma::load_matrix_sync(fbl, smb + 7680 + (ni * 16) * SA + ks * 16, SA);
            wmma::mma_sync(acc, fah, fbh, acc);
            wmma::mma_sync(acc, fah, fbl, acc);
            wmma::mma_sync(acc, fal, fbh, acc);
        }
        wmma::store_matrix_sync(s + (mi * 16) * SC + ni * 16, acc, SC, wmma::mem_row_major);
    }
    __syncthreads();

    // Row softmax: 4 threads per row (consecutive lanes), shfl reduce
    {
        int row = tid >> 2, l4 = tid & 3;
        float* sr = s + row * SC;
        float m = -1e30f;
        #pragma unroll
        for (int c = 0; c < 16; c++) m = fmaxf(m, sr[l4 * 16 + c]);
        m = fmaxf(m, __shfl_xor_sync(0xFFFFFFFF, m, 1));
        m = fmaxf(m, __shfl_xor_sync(0xFFFFFFFF, m, 2));
        float sum = 0.f;
        float e[16];
        #pragma unroll
        for (int c = 0; c < 16; c++) { e[c] = expf(sr[l4 * 16 + c] - m); sum += e[c]; }
        sum += __shfl_xor_sync(0xFFFFFFFF, sum, 1);
        sum += __shfl_xor_sync(0xFFFFFFFF, sum, 2);
        float inv = 1.f / sum;
        #pragma unroll
        for (int c = 0; c < 16; c++) {
            float a = e[c] * inv;
            bf16 h = __float2bfloat16(a);
            ah[row * SB + l4 * 16 + c] = h;
            al[row * SB + l4 * 16 + c] = __float2bfloat16(a - __bfloat162float(h));
        }
    }
    __syncthreads();

    // O = A V : 8 frags (4x2), one per warp; stage f32 to smem
    {
        int mi = warp >> 1, ni = warp & 1;
        wmma::fragment<wmma::accumulator, 16, 16, 16, float> acc;
        wmma::fill_fragment(acc, 0.0f);
        #pragma unroll
        for (int ks = 0; ks < 4; ks++) {
            wmma::fragment<wmma::matrix_a, 16, 16, 16, bf16, wmma::row_major> fah, fal;
            wmma::fragment<wmma::matrix_b, 16, 16, 16, bf16, wmma::row_major> fbh, fbl;
            wmma::load_matrix_sync(fah, ah + (mi * 16) * SB + ks * 16, SB);
            wmma::load_matrix_sync(fal, al + (mi * 16) * SB + ks * 16, SB);
            wmma::load_matrix_sync(fbh, smb + 10240 + (ks * 16) * SA + ni * 16, SA);
            wmma::load_matrix_sync(fbl, smb + 12800 + (ks * 16) * SA + ni * 16, SA);
            wmma::mma_sync(acc, fah, fbh, acc);
            wmma::mma_sync(acc, fah, fbl, acc);
            wmma::mma_sync(acc, fal, fbh, acc);
        }
        wmma::store_matrix_sync(s + (mi * 16) * 36 + ni * 16, acc, 36, wmma::mem_row_major);
    }
    __syncthreads();

    // split O to g_aoh/g_aol (uint4 = 8 bf16); rows windowed, cols head*32..+31
    {
        int row = tid >> 2, c8 = (tid & 3) * 8;
        float4 v0 = *reinterpret_cast<const float4*>(s + row * 36 + c8);
        float4 v1 = *reinterpret_cast<const float4*>(s + row * 36 + c8 + 4);
        uint2 ph0, pl0, ph1, pl1;
        split_pack(v0, ph0, pl0);
        split_pack(v1, ph1, pl1);
        size_t di = (size_t)(wid * 64 + row) * 64 + head * 4 + (tid & 3);
        g_aoh[di] = make_uint4(ph0.x, ph0.y, ph1.x, ph1.y);
        g_aol[di] = make_uint4(pl0.x, pl0.y, pl1.x, pl1.y);
    }
}

extern "C" void kernel_launch(void* const* d_in, const int* in_sizes, int n_in,
                              void* d_out, int out_size)
{
    (void)in_sizes; (void)n_in; (void)out_size;
    const float* x      = (const float*)d_in[0];
    const float* qkv_w  = (const float*)d_in[1];
    const float* qkv_b  = (const float*)d_in[2];
    // d_in[3], d_in[4] (kv_w, kv_b) are dead code in the reference output
    const float* proj_w = (const float*)d_in[5];
    const float* proj_b = (const float*)d_in[6];
    float* out = (float*)d_out;

    const int gemm_smem = 2 * STAGE_B;            // 59392 B (csm 34816 fits)
    const int attn_smem = 30720 + 64 * SC * 4;    // 48128 B

    cudaFuncSetAttribute(gemm_kernel<true>,
                         cudaFuncAttributeMaxDynamicSharedMemorySize, gemm_smem);
    cudaFuncSetAttribute(gemm_kernel<false>,
                         cudaFuncAttributeMaxDynamicSharedMemorySize, gemm_smem);

    split_x_kernel<<<NTOK * DIM / 8 / 256, 256>>>(x);
    split_w_kernel<<<DIM * NQKV / 8 / 256, 256>>>(qkv_w, 0);
    split_w_kernel<<<DIM * DIM  / 8 / 256, 256>>>(proj_w, 1);

    gemm_kernel<true>
        <<<dim3(NTOK / BM, NQKV / BN), 256, gemm_smem>>>(qkv_b, nullptr);
    attn_kernel<<<dim3(NWIN, NH), 256, attn_smem>>>();
    gemm_kernel<false>
        <<<dim3(NTOK / BM, DIM / BN), 256, gemm_smem>>>(proj_b, out);
}

// round 10
// speedup vs baseline: 9.3469x; 1.5150x over previous
#include <cuda_runtime.h>
#include <cuda_bf16.h>
#include <cuda_fp16.h>
#include <mma.h>
#include <cstdint>

using namespace nvcuda;
typedef __nv_bfloat16 bf16;

#define DIM    512
#define NH     16
#define HD     32
#define NWIN   512      // 8 batches * 8*8 windows
#define NTOK   32768    // 512 windows * 64 tokens
#define NQKV   1536
#define WSCALE 0.17677669529663687f   // 32^-0.5

// GEMM tiling (128x64 tile, 4 acc frags/thread)
#define BM 128
#define BN 64
#define BK 32
#define SA 40    // A smem row stride (fp16 elems)
#define SB 72    // B smem row stride (fp16 elems)
#define SC 68    // C epilogue stride (f32)
#define STAGE_B 19456          // bytes per smem stage (A 10240 + B 9216)
#define STAGE_E 9728           // fp16 elems per stage

// Scratch (__device__ globals). RULE: referenced ONLY from device code.
__device__ float g_q[(size_t)NWIN * NH * 64 * HD];
__device__ float g_k[(size_t)NWIN * NH * 64 * HD];
__device__ float g_v[(size_t)NWIN * NH * 64 * HD];
// fp16 operands: A-side single precision, W-side hi/lo split (uint4 = 8 halves)
__device__ uint4 g_xh [(size_t)NTOK * DIM / 8];   // x, windowed rows, fp16
__device__ uint4 g_aoh[(size_t)NTOK * DIM / 8];   // attention out, fp16
__device__ uint4 g_wqh[(size_t)DIM * NQKV / 8];
__device__ uint4 g_wql[(size_t)DIM * NQKV / 8];
__device__ uint4 g_wph[(size_t)DIM * DIM / 8];
__device__ uint4 g_wpl[(size_t)DIM * DIM / 8];

__device__ __forceinline__ unsigned short usb(bf16 v) { return __bfloat16_as_ushort(v); }
__device__ __forceinline__ unsigned short ush(__half v) { return __half_as_ushort(v); }

// bf16 split (attention internals — proven path)
__device__ __forceinline__ void split_pack(float4 v, uint2& ph, uint2& pl) {
    bf16 h0 = __float2bfloat16(v.x), h1 = __float2bfloat16(v.y);
    bf16 h2 = __float2bfloat16(v.z), h3 = __float2bfloat16(v.w);
    bf16 l0 = __float2bfloat16(v.x - __bfloat162float(h0));
    bf16 l1 = __float2bfloat16(v.y - __bfloat162float(h1));
    bf16 l2 = __float2bfloat16(v.z - __bfloat162float(h2));
    bf16 l3 = __float2bfloat16(v.w - __bfloat162float(h3));
    ph.x = usb(h0) | ((unsigned)usb(h1) << 16);
    ph.y = usb(h2) | ((unsigned)usb(h3) << 16);
    pl.x = usb(l0) | ((unsigned)usb(l1) << 16);
    pl.y = usb(l2) | ((unsigned)usb(l3) << 16);
}

// pack 8 floats -> 8 fp16 (single precision)
__device__ __forceinline__ uint4 pack8_fp16(float4 v0, float4 v1) {
    uint4 o;
    o.x = ush(__float2half_rn(v0.x)) | ((unsigned)ush(__float2half_rn(v0.y)) << 16);
    o.y = ush(__float2half_rn(v0.z)) | ((unsigned)ush(__float2half_rn(v0.w)) << 16);
    o.z = ush(__float2half_rn(v1.x)) | ((unsigned)ush(__float2half_rn(v1.y)) << 16);
    o.w = ush(__float2half_rn(v1.z)) | ((unsigned)ush(__float2half_rn(v1.w)) << 16);
    return o;
}
// split 8 floats -> fp16 hi + fp16 lo
__device__ __forceinline__ void split8_fp16(float4 v0, float4 v1, uint4& hi, uint4& lo) {
    float f[8] = {v0.x, v0.y, v0.z, v0.w, v1.x, v1.y, v1.z, v1.w};
    unsigned short h[8], l[8];
    #pragma unroll
    for (int i = 0; i < 8; i++) {
        __half hh = __float2half_rn(f[i]);
        h[i] = ush(hh);
        l[i] = ush(__float2half_rn(f[i] - __half2float(hh)));
    }
    hi = make_uint4(h[0] | ((unsigned)h[1] << 16), h[2] | ((unsigned)h[3] << 16),
                    h[4] | ((unsigned)h[5] << 16), h[6] | ((unsigned)h[7] << 16));
    lo = make_uint4(l[0] | ((unsigned)l[1] << 16), l[2] | ((unsigned)l[3] << 16),
                    l[4] | ((unsigned)l[5] << 16), l[6] | ((unsigned)l[7] << 16));
}

__device__ __forceinline__ int win_token(int r) {
    int wid = r >> 6, n = r & 63;
    int b = wid >> 6, wy = (wid >> 3) & 7, wx = wid & 7;
    int h = wy * 8 + (n >> 3), w = wx * 8 + (n & 7);
    return (b << 12) + (h << 6) + w;
}

__device__ __forceinline__ uint32_t smem_u32(const void* p) {
    uint32_t a;
    asm("{ .reg .u64 t; cvta.to.shared.u64 t, %1; cvt.u32.u64 %0, t; }" : "=r"(a) : "l"(p));
    return a;
}
#define CP_ASYNC16(dst, src) \
    asm volatile("cp.async.cg.shared.global [%0], [%1], 16;" :: "r"(dst), "l"(src))
#define CP_COMMIT()  asm volatile("cp.async.commit_group;" ::: "memory")
#define CP_WAIT(n)   asm volatile("cp.async.wait_group %0;" :: "n"(n) : "memory")

// x -> fp16 single, WINDOWED row order
__global__ void split_x_kernel(const float* __restrict__ x) {
    int idx = blockIdx.x * 256 + threadIdx.x;   // uint4 index (8 halves)
    int r = idx >> 6, c8 = idx & 63;
    int t = win_token(r);
    const float* src = x + (size_t)t * DIM + c8 * 8;
    float4 v0 = *reinterpret_cast<const float4*>(src);
    float4 v1 = *reinterpret_cast<const float4*>(src + 4);
    g_xh[idx] = pack8_fp16(v0, v1);
}

// weight matrix -> fp16 hi/lo (which: 0=qkv_w, 1=proj_w)
__global__ void split_w_kernel(const float* __restrict__ w, int which) {
    int idx = blockIdx.x * 256 + threadIdx.x;
    float4 v0 = *reinterpret_cast<const float4*>(w + (size_t)idx * 8);
    float4 v1 = *reinterpret_cast<const float4*>(w + (size_t)idx * 8 + 4);
    uint4 hi, lo;
    split8_fp16(v0, v1, hi, lo);
    uint4* h = which ? g_wph : g_wqh;
    uint4* l = which ? g_wpl : g_wql;
    h[idx] = hi;
    l[idx] = lo;
}

// C = A @ W + bias; fp16 2-MMA scheme: C = ah*(wh + wl), fp32 accum.
// Double-buffered smem, all tile loads via cp.async.
template<bool QKV>
__global__ void gemm_kernel(const float* __restrict__ bias, float* __restrict__ out)
{
    constexpr int NCOLS = QKV ? NQKV : DIM;
    extern __shared__ __align__(16) char smraw[];
    __half* smb0 = reinterpret_cast<__half*>(smraw);
    const uint32_t sm_addr = smem_u32(smraw);

    int tid  = threadIdx.x;
    int warp = tid >> 5;
    int wm = warp >> 1, wn = warp & 1;
    int rbase = blockIdx.x * BM;
    int nbase = blockIdx.y * BN;

    const uint4* ah = QKV ? g_xh  : g_aoh;   // device-code refs
    const uint4* wh = QKV ? g_wqh : g_wph;
    const uint4* wl = QKV ? g_wql : g_wpl;

    wmma::fragment<wmma::accumulator, 16, 16, 16, float> acc[2][2];
    #pragma unroll
    for (int i = 0; i < 2; i++)
        #pragma unroll
        for (int j = 0; j < 2; j++) wmma::fill_fragment(acc[i][j], 0.0f);

    // per-thread copy coords
    int ai0 = tid >> 2,          ac = tid & 3;     // A: 512 chunks, 2/thread
    int ai1 = (tid + 256) >> 2;
    int brow = tid >> 3,         bc4 = tid & 7;    // B: 256 chunks each (hi,lo)

    auto issue = [&](int kt) {
        uint32_t st = sm_addr + (kt & 1) * STAGE_B;
        size_t ga0 = (size_t)(rbase + ai0) * (DIM / 8) + kt * 4 + ac;
        size_t ga1 = (size_t)(rbase + ai1) * (DIM / 8) + kt * 4 + ac;
        CP_ASYNC16(st + ai0 * 80 + ac * 16, ah + ga0);
        CP_ASYNC16(st + ai1 * 80 + ac * 16, ah + ga1);
        size_t gb = ((size_t)(kt * BK + brow) * NCOLS + nbase) / 8 + bc4;
        CP_ASYNC16(st + 10240 + brow * 144 + bc4 * 16, wh + gb);
        CP_ASYNC16(st + 14848 + brow * 144 + bc4 * 16, wl + gb);
        CP_COMMIT();
    };

    issue(0);

    const int NKT = DIM / BK;   // 16
    for (int kt = 0; kt < NKT; kt++) {
        __syncthreads();
        if (kt + 1 < NKT) { issue(kt + 1); CP_WAIT(1); }
        else              { CP_WAIT(0); }
        __syncthreads();

        __half* smb = smb0 + (kt & 1) * STAGE_E;
        #pragma unroll
        for (int ks = 0; ks < 2; ks++) {
            wmma::fragment<wmma::matrix_a, 16, 16, 16, __half, wmma::row_major> fa[2];
            wmma::fragment<wmma::matrix_b, 16, 16, 16, __half, wmma::row_major> fbh[2], fbl[2];
            #pragma unroll
            for (int i = 0; i < 2; i++)
                wmma::load_matrix_sync(fa[i], smb + (wm * 32 + i * 16) * SA + ks * 16, SA);
            #pragma unroll
            for (int j = 0; j < 2; j++) {
                int col = wn * 32 + j * 16;
                wmma::load_matrix_sync(fbh[j], smb + 5120 + (ks * 16) * SB + col, SB);
                wmma::load_matrix_sync(fbl[j], smb + 7424 + (ks * 16) * SB + col, SB);
            }
            #pragma unroll
            for (int i = 0; i < 2; i++)
                #pragma unroll
                for (int j = 0; j < 2; j++) {
                    wmma::mma_sync(acc[i][j], fa[i], fbh[j], acc[i][j]);
                    wmma::mma_sync(acc[i][j], fa[i], fbl[j], acc[i][j]);
                }
        }
    }
    __syncthreads();
    float* csm = reinterpret_cast<float*>(smraw);
    #pragma unroll
    for (int i = 0; i < 2; i++)
        #pragma unroll
        for (int j = 0; j < 2; j++)
            wmma::store_matrix_sync(csm + (wm * 32 + i * 16) * SC + wn * 32 + j * 16,
                                    acc[i][j], SC, wmma::mem_row_major);
    __syncthreads();

    // Epilogue: 128x64 tile, 32 elems/thread
    for (int s4 = 0; s4 < (BM * BN) / 256; s4++) {
        int idx = tid + s4 * 256;
        int i = idx >> 6, cl = idx & 63;
        int r = rbase + i;
        int c = nbase + cl;
        float v = csm[i * SC + cl] + bias[c];
        if (QKV) {
            int wid = r >> 6, n = r & 63;
            int which = c >> 9;           // 0=q 1=k 2=v
            int cc = c & 511;
            int head = cc >> 5, d = cc & 31;
            float o;
            if (which < 2) {
                int j16 = d & 15;
                int g   = d >> 4;
                int pos = g ? (n & 7) : (n >> 3);
                int jj  = j16 & 7;
                float invf = exp2f(-1.6609640474436813f * (float)jj); // 10000^(-jj/8)
                float ang = (float)pos * invf;
                float sn, cs;
                sincosf(ang, &sn, &cs);
                int off = (j16 < 8) ? 8 : -8;
                float vp = csm[i * SC + cl + off] + bias[c + off];
                o = (j16 < 8) ? (v * cs - vp * sn) : (v * cs + vp * sn);
            } else {
                o = v;
            }
            float* dst = (which == 0) ? g_q : (which == 1) ? g_k : g_v;
            dst[(((size_t)wid * NH + head) * 64 + n) * HD + d] = o;
        } else {
            int t = win_token(r);
            out[(size_t)t * DIM + c] = v;
        }
    }
}

// One CTA per (window, head): S = (Q*scale) K^T, softmax, O = A V.
// Internals bf16-3 (proven). Output written as fp16 single for proj GEMM.
__global__ void attn_kernel()
{
    extern __shared__ __align__(16) char smraw[];
    bf16* smb = reinterpret_cast<bf16*>(smraw);
    // bf16-elem offsets: qh 0, ql 2560, kh 5120, kl 7680, vh 10240, vl 12800
    float* s = reinterpret_cast<float*>(smraw + 30720);   // 64x68 f32
    bf16* ah = smb;                                        // overlay (dead after S)
    bf16* al = smb + 4608;

    int tid = threadIdx.x, warp = tid >> 5;
    int wid = blockIdx.x, head = blockIdx.y;
    size_t base = ((size_t)wid * NH + head) * (64 * HD);
    const float* qg = g_q + base;
    const float* kg = g_k + base;
    const float* vg = g_v + base;

    #pragma unroll
    for (int s4 = 0; s4 < 2; s4++) {
        int e = tid + s4 * 256;
        int n = e >> 3, d4 = e & 7;
        float4 v; uint2 ph, pl;
        v = *reinterpret_cast<const float4*>(qg + e * 4);
        v.x *= WSCALE; v.y *= WSCALE; v.z *= WSCALE; v.w *= WSCALE;
        split_pack(v, ph, pl);
        *reinterpret_cast<uint2*>(smb + n * SA + d4 * 4)        = ph;
        *reinterpret_cast<uint2*>(smb + 2560 + n * SA + d4 * 4) = pl;
        v = *reinterpret_cast<const float4*>(kg + e * 4);
        split_pack(v, ph, pl);
        *reinterpret_cast<uint2*>(smb + 5120 + n * SA + d4 * 4) = ph;
        *reinterpret_cast<uint2*>(smb + 7680 + n * SA + d4 * 4) = pl;
        v = *reinterpret_cast<const float4*>(vg + e * 4);
        split_pack(v, ph, pl);
        *reinterpret_cast<uint2*>(smb + 10240 + n * SA + d4 * 4) = ph;
        *reinterpret_cast<uint2*>(smb + 12800 + n * SA + d4 * 4) = pl;
    }
    __syncthreads();

    // S = Q K^T : 16 frags of 16x16, 2 per warp
    #pragma unroll
    for (int fi = 0; fi < 2; fi++) {
        int f = warp + fi * 8;
        int mi = f >> 2, ni = f & 3;
        wmma::fragment<wmma::accumulator, 16, 16, 16, float> acc;
        wmma::fill_fragment(acc, 0.0f);
        #pragma unroll
        for (int ks = 0; ks < 2; ks++) {
            wmma::fragment<wmma::matrix_a, 16, 16, 16, bf16, wmma::row_major> fah, fal;
            wmma::fragment<wmma::matrix_b, 16, 16, 16, bf16, wmma::col_major> fbh, fbl;
            wmma::load_matrix_sync(fah, smb + (mi * 16) * SA + ks * 16, SA);
            wmma::load_matrix_sync(fal, smb + 2560 + (mi * 16) * SA + ks * 16, SA);
            wmma::load_matrix_sync(fbh, smb + 5120 + (ni * 16) * SA + ks * 16, SA);
            wmma::load_matrix_sync(fbl, smb + 7680 + (ni * 16) * SA + ks * 16, SA);
            wmma::mma_sync(acc, fah, fbh, acc);
            wmma::mma_sync(acc, fah, fbl, acc);
            wmma::mma_sync(acc, fal, fbh, acc);
        }
        wmma::store_matrix_sync(s + (mi * 16) * SC + ni * 16, acc, SC, wmma::mem_row_major);
    }
    __syncthreads();

    // Row softmax: 4 threads per row, shfl reduce
    {
        int row = tid >> 2, l4 = tid & 3;
        float* sr = s + row * SC;
        float m = -1e30f;
        #pragma unroll
        for (int c = 0; c < 16; c++) m = fmaxf(m, sr[l4 * 16 + c]);
        m = fmaxf(m, __shfl_xor_sync(0xFFFFFFFF, m, 1));
        m = fmaxf(m, __shfl_xor_sync(0xFFFFFFFF, m, 2));
        float sum = 0.f;
        float e[16];
        #pragma unroll
        for (int c = 0; c < 16; c++) { e[c] = expf(sr[l4 * 16 + c] - m); sum += e[c]; }
        sum += __shfl_xor_sync(0xFFFFFFFF, sum, 1);
        sum += __shfl_xor_sync(0xFFFFFFFF, sum, 2);
        float inv = 1.f / sum;
        #pragma unroll
        for (int c = 0; c < 16; c++) {
            float a = e[c] * inv;
            bf16 h = __float2bfloat16(a);
            ah[row * 72 + l4 * 16 + c] = h;
            al[row * 72 + l4 * 16 + c] = __float2bfloat16(a - __bfloat162float(h));
        }
    }
    __syncthreads();

    // O = A V : 8 frags (4x2), one per warp; stage f32 to smem
    {
        int mi = warp >> 1, ni = warp & 1;
        wmma::fragment<wmma::accumulator, 16, 16, 16, float> acc;
        wmma::fill_fragment(acc, 0.0f);
        #pragma unroll
        for (int ks = 0; ks < 4; ks++) {
            wmma::fragment<wmma::matrix_a, 16, 16, 16, bf16, wmma::row_major> fah, fal;
            wmma::fragment<wmma::matrix_b, 16, 16, 16, bf16, wmma::row_major> fbh, fbl;
            wmma::load_matrix_sync(fah, ah + (mi * 16) * 72 + ks * 16, 72);
            wmma::load_matrix_sync(fal, al + (mi * 16) * 72 + ks * 16, 72);
            wmma::load_matrix_sync(fbh, smb + 10240 + (ks * 16) * SA + ni * 16, SA);
            wmma::load_matrix_sync(fbl, smb + 12800 + (ks * 16) * SA + ni * 16, SA);
            wmma::mma_sync(acc, fah, fbh, acc);
            wmma::mma_sync(acc, fah, fbl, acc);
            wmma::mma_sync(acc, fal, fbh, acc);
        }
        wmma::store_matrix_sync(s + (mi * 16) * 36 + ni * 16, acc, 36, wmma::mem_row_major);
    }
    __syncthreads();

    // O -> g_aoh fp16 single (uint4 = 8 halves); rows windowed, cols head*32..+31
    {
        int row = tid >> 2, c8 = (tid & 3) * 8;
        float4 v0 = *reinterpret_cast<const float4*>(s + row * 36 + c8);
        float4 v1 = *reinterpret_cast<const float4*>(s + row * 36 + c8 + 4);
        size_t di = (size_t)(wid * 64 + row) * 64 + head * 4 + (tid & 3);
        g_aoh[di] = pack8_fp16(v0, v1);
    }
}

extern "C" void kernel_launch(void* const* d_in, const int* in_sizes, int n_in,
                              void* d_out, int out_size)
{
    (void)in_sizes; (void)n_in; (void)out_size;
    const float* x      = (const float*)d_in[0];
    const float* qkv_w  = (const float*)d_in[1];
    const float* qkv_b  = (const float*)d_in[2];
    // d_in[3], d_in[4] (kv_w, kv_b) are dead code in the reference output
    const float* proj_w = (const float*)d_in[5];
    const float* proj_b = (const float*)d_in[6];
    float* out = (float*)d_out;

    const int gemm_smem = 2 * STAGE_B;            // 38912 B (< 48KB default)
    const int attn_smem = 30720 + 64 * SC * 4;    // 48128 B (< 48KB default limit)

    split_x_kernel<<<NTOK * DIM / 8 / 256, 256>>>(x);
    split_w_kernel<<<DIM * NQKV / 8 / 256, 256>>>(qkv_w, 0);
    split_w_kernel<<<DIM * DIM  / 8 / 256, 256>>>(proj_w, 1);

    gemm_kernel<true>
        <<<dim3(NTOK / BM, NQKV / BN), 256, gemm_smem>>>(qkv_b, nullptr);
    attn_kernel<<<dim3(NWIN, NH), 256, attn_smem>>>();
    gemm_kernel<false>
        <<<dim3(NTOK / BM, DIM / BN), 256, gemm_smem>>>(proj_b, out);
}

// round 11
// speedup vs baseline: 11.2266x; 1.2011x over previous
#include <cuda_runtime.h>
#include <cuda_bf16.h>
#include <cuda_fp16.h>
#include <mma.h>
#include <cstdint>

using namespace nvcuda;
typedef __nv_bfloat16 bf16;

#define DIM    512
#define NH     16
#define HD     32
#define NWIN   512      // 8 batches * 8*8 windows
#define NTOK   32768    // 512 windows * 64 tokens
#define NQKV   1536
#define WSCALE 0.17677669529663687f   // 32^-0.5

// GEMM tiling: 128x64 tile, BK=64, double-buffered
#define BM 128
#define BN 64
#define BK 64
#define SA 72    // A smem row stride (fp16 elems)  -- 144 B, 16B-aligned
#define SB 72    // B smem row stride (fp16 elems)
#define SC 68    // C epilogue stride (f32)
#define STAGE_B 36864          // bytes per stage: A 18432 + Bh 9216 + Bl 9216
#define STAGE_E 18432          // fp16 elems per stage
// attention smem strides
#define ASA 40

// Scratch (__device__ globals). RULE: referenced ONLY from device code.
__device__ float g_q[(size_t)NWIN * NH * 64 * HD];
__device__ float g_k[(size_t)NWIN * NH * 64 * HD];
__device__ float g_v[(size_t)NWIN * NH * 64 * HD];
// fp16 operands: A-side single precision, W-side hi/lo split (uint4 = 8 halves)
__device__ uint4 g_xh [(size_t)NTOK * DIM / 8];   // x, windowed rows, fp16
__device__ uint4 g_aoh[(size_t)NTOK * DIM / 8];   // attention out, fp16
__device__ uint4 g_wqh[(size_t)DIM * NQKV / 8];
__device__ uint4 g_wql[(size_t)DIM * NQKV / 8];
__device__ uint4 g_wph[(size_t)DIM * DIM / 8];
__device__ uint4 g_wpl[(size_t)DIM * DIM / 8];

__device__ __forceinline__ unsigned short usb(bf16 v) { return __bfloat16_as_ushort(v); }
__device__ __forceinline__ unsigned short ush(__half v) { return __half_as_ushort(v); }

// bf16 split (attention internals — proven path)
__device__ __forceinline__ void split_pack(float4 v, uint2& ph, uint2& pl) {
    bf16 h0 = __float2bfloat16(v.x), h1 = __float2bfloat16(v.y);
    bf16 h2 = __float2bfloat16(v.z), h3 = __float2bfloat16(v.w);
    bf16 l0 = __float2bfloat16(v.x - __bfloat162float(h0));
    bf16 l1 = __float2bfloat16(v.y - __bfloat162float(h1));
    bf16 l2 = __float2bfloat16(v.z - __bfloat162float(h2));
    bf16 l3 = __float2bfloat16(v.w - __bfloat162float(h3));
    ph.x = usb(h0) | ((unsigned)usb(h1) << 16);
    ph.y = usb(h2) | ((unsigned)usb(h3) << 16);
    pl.x = usb(l0) | ((unsigned)usb(l1) << 16);
    pl.y = usb(l2) | ((unsigned)usb(l3) << 16);
}

__device__ __forceinline__ uint4 pack8_fp16(float4 v0, float4 v1) {
    uint4 o;
    o.x = ush(__float2half_rn(v0.x)) | ((unsigned)ush(__float2half_rn(v0.y)) << 16);
    o.y = ush(__float2half_rn(v0.z)) | ((unsigned)ush(__float2half_rn(v0.w)) << 16);
    o.z = ush(__float2half_rn(v1.x)) | ((unsigned)ush(__float2half_rn(v1.y)) << 16);
    o.w = ush(__float2half_rn(v1.z)) | ((unsigned)ush(__float2half_rn(v1.w)) << 16);
    return o;
}
__device__ __forceinline__ void split8_fp16(float4 v0, float4 v1, uint4& hi, uint4& lo) {
    float f[8] = {v0.x, v0.y, v0.z, v0.w, v1.x, v1.y, v1.z, v1.w};
    unsigned short h[8], l[8];
    #pragma unroll
    for (int i = 0; i < 8; i++) {
        __half hh = __float2half_rn(f[i]);
        h[i] = ush(hh);
        l[i] = ush(__float2half_rn(f[i] - __half2float(hh)));
    }
    hi = make_uint4(h[0] | ((unsigned)h[1] << 16), h[2] | ((unsigned)h[3] << 16),
                    h[4] | ((unsigned)h[5] << 16), h[6] | ((unsigned)h[7] << 16));
    lo = make_uint4(l[0] | ((unsigned)l[1] << 16), l[2] | ((unsigned)l[3] << 16),
                    l[4] | ((unsigned)l[5] << 16), l[6] | ((unsigned)l[7] << 16));
}

__device__ __forceinline__ int win_token(int r) {
    int wid = r >> 6, n = r & 63;
    int b = wid >> 6, wy = (wid >> 3) & 7, wx = wid & 7;
    int h = wy * 8 + (n >> 3), w = wx * 8 + (n & 7);
    return (b << 12) + (h << 6) + w;
}

__device__ __forceinline__ uint32_t smem_u32(const void* p) {
    uint32_t a;
    asm("{ .reg .u64 t; cvta.to.shared.u64 t, %1; cvt.u32.u64 %0, t; }" : "=r"(a) : "l"(p));
    return a;
}
#define CP_ASYNC16(dst, src) \
    asm volatile("cp.async.cg.shared.global [%0], [%1], 16;" :: "r"(dst), "l"(src))
#define CP_COMMIT()  asm volatile("cp.async.commit_group;" ::: "memory")
#define CP_WAIT(n)   asm volatile("cp.async.wait_group %0;" :: "n"(n) : "memory")

// x -> fp16 single, WINDOWED row order
__global__ void split_x_kernel(const float* __restrict__ x) {
    int idx = blockIdx.x * 256 + threadIdx.x;   // uint4 index (8 halves)
    int r = idx >> 6, c8 = idx & 63;
    int t = win_token(r);
    const float* src = x + (size_t)t * DIM + c8 * 8;
    float4 v0 = *reinterpret_cast<const float4*>(src);
    float4 v1 = *reinterpret_cast<const float4*>(src + 4);
    g_xh[idx] = pack8_fp16(v0, v1);
}

// weight matrix -> fp16 hi/lo (which: 0=qkv_w, 1=proj_w)
__global__ void split_w_kernel(const float* __restrict__ w, int which) {
    int idx = blockIdx.x * 256 + threadIdx.x;
    float4 v0 = *reinterpret_cast<const float4*>(w + (size_t)idx * 8);
    float4 v1 = *reinterpret_cast<const float4*>(w + (size_t)idx * 8 + 4);
    uint4 hi, lo;
    split8_fp16(v0, v1, hi, lo);
    uint4* h = which ? g_wph : g_wqh;
    uint4* l = which ? g_wpl : g_wql;
    h[idx] = hi;
    l[idx] = lo;
}

// C = A @ W + bias; fp16 2-MMA scheme: C = ah*(wh + wl), fp32 accum.
// BK=64 double-buffered cp.async pipeline; RoPE via smem table.
template<bool QKV>
__global__ void __launch_bounds__(256, 3)
gemm_kernel(const float* __restrict__ bias, float* __restrict__ out)
{
    constexpr int NCOLS = QKV ? NQKV : DIM;
    extern __shared__ __align__(16) char smraw[];
    __half* smb0 = reinterpret_cast<__half*>(smraw);
    const uint32_t sm_addr = smem_u32(smraw);
    __shared__ float2 rope[64];

    int tid  = threadIdx.x;
    int warp = tid >> 5;
    int wm = warp >> 1, wn = warp & 1;
    int rbase = blockIdx.x * BM;
    int nbase = blockIdx.y * BN;

    const uint4* ahp = QKV ? g_xh  : g_aoh;   // device-code refs
    const uint4* whp = QKV ? g_wqh : g_wph;
    const uint4* wlp = QKV ? g_wql : g_wpl;

    if (QKV && tid < 64) {
        int pos = tid >> 3, jj = tid & 7;
        float invf = exp2f(-1.6609640474436813f * (float)jj);  // 10000^(-jj/8)
        float sn, cs;
        sincosf((float)pos * invf, &sn, &cs);
        rope[tid] = make_float2(cs, sn);
    }

    wmma::fragment<wmma::accumulator, 16, 16, 16, float> acc[2][2];
    #pragma unroll
    for (int i = 0; i < 2; i++)
        #pragma unroll
        for (int j = 0; j < 2; j++) wmma::fill_fragment(acc[i][j], 0.0f);

    auto issue = [&](int kt) {
        uint32_t st = sm_addr + (kt & 1) * STAGE_B;
        // A: 128 rows x 8 uint4 (1024 total, 4/thread)
        #pragma unroll
        for (int s = 0; s < 4; s++) {
            int idx = tid + s * 256;
            int row = idx >> 3, c = idx & 7;
            size_t ga = (size_t)(rbase + row) * (DIM / 8) + kt * 8 + c;
            CP_ASYNC16(st + row * 144 + c * 16, ahp + ga);
        }
        // B: 64 rows x 8 uint4, hi + lo (512 each, 2/thread each)
        #pragma unroll
        for (int s = 0; s < 2; s++) {
            int idx = tid + s * 256;
            int row = idx >> 3, c = idx & 7;
            size_t gb = ((size_t)(kt * BK + row) * NCOLS + nbase) / 8 + c;
            CP_ASYNC16(st + 18432 + row * 144 + c * 16, whp + gb);
            CP_ASYNC16(st + 27648 + row * 144 + c * 16, wlp + gb);
        }
        CP_COMMIT();
    };

    issue(0);

    const int NKT = DIM / BK;   // 8
    for (int kt = 0; kt < NKT; kt++) {
        __syncthreads();
        if (kt + 1 < NKT) { issue(kt + 1); CP_WAIT(1); }
        else              { CP_WAIT(0); }
        __syncthreads();

        __half* smb = smb0 + (kt & 1) * STAGE_E;
        #pragma unroll
        for (int ks = 0; ks < 4; ks++) {
            wmma::fragment<wmma::matrix_a, 16, 16, 16, __half, wmma::row_major> fa[2];
            #pragma unroll
            for (int i = 0; i < 2; i++)
                wmma::load_matrix_sync(fa[i], smb + (wm * 32 + i * 16) * SA + ks * 16, SA);
            #pragma unroll
            for (int j = 0; j < 2; j++) {
                wmma::fragment<wmma::matrix_b, 16, 16, 16, __half, wmma::row_major> fbh, fbl;
                int col = wn * 32 + j * 16;
                wmma::load_matrix_sync(fbh, smb + 9216 + (ks * 16) * SB + col, SB);
                wmma::load_matrix_sync(fbl, smb + 13824 + (ks * 16) * SB + col, SB);
                #pragma unroll
                for (int i = 0; i < 2; i++) {
                    wmma::mma_sync(acc[i][j], fa[i], fbh, acc[i][j]);
                    wmma::mma_sync(acc[i][j], fa[i], fbl, acc[i][j]);
                }
            }
        }
    }
    __syncthreads();
    float* csm = reinterpret_cast<float*>(smraw);
    #pragma unroll
    for (int i = 0; i < 2; i++)
        #pragma unroll
        for (int j = 0; j < 2; j++)
            wmma::store_matrix_sync(csm + (wm * 32 + i * 16) * SC + wn * 32 + j * 16,
                                    acc[i][j], SC, wmma::mem_row_major);
    __syncthreads();

    // Epilogue: 128x64 tile, 32 elems/thread; RoPE from smem table
    for (int s4 = 0; s4 < (BM * BN) / 256; s4++) {
        int idx = tid + s4 * 256;
        int i = idx >> 6, cl = idx & 63;
        int r = rbase + i;
        int c = nbase + cl;
        float v = csm[i * SC + cl] + bias[c];
        if (QKV) {
            int wid = r >> 6, n = r & 63;
            int which = c >> 9;           // 0=q 1=k 2=v
            int cc = c & 511;
            int head = cc >> 5, d = cc & 31;
            float o;
            if (which < 2) {
                int j16 = d & 15;
                int g   = d >> 4;
                int pos = g ? (n & 7) : (n >> 3);
                float2 csn = rope[pos * 8 + (j16 & 7)];
                int off = (j16 < 8) ? 8 : -8;
                float vp = csm[i * SC + cl + off] + bias[c + off];
                o = (j16 < 8) ? (v * csn.x - vp * csn.y) : (v * csn.x + vp * csn.y);
            } else {
                o = v;
            }
            float* dst = (which == 0) ? g_q : (which == 1) ? g_k : g_v;
            dst[(((size_t)wid * NH + head) * 64 + n) * HD + d] = o;
        } else {
            int t = win_token(r);
            out[(size_t)t * DIM + c] = v;
        }
    }
}

// One CTA per (window, head): S = (Q*scale) K^T, softmax, O = A V.
// Internals bf16-3 (proven). Output written as fp16 single for proj GEMM.
__global__ void attn_kernel()
{
    extern __shared__ __align__(16) char smraw[];
    bf16* smb = reinterpret_cast<bf16*>(smraw);
    // bf16-elem offsets: qh 0, ql 2560, kh 5120, kl 7680, vh 10240, vl 12800
    float* s = reinterpret_cast<float*>(smraw + 30720);   // 64x68 f32
    bf16* ah = smb;                                        // overlay (dead after S)
    bf16* al = smb + 4608;

    int tid = threadIdx.x, warp = tid >> 5;
    int wid = blockIdx.x, head = blockIdx.y;
    size_t base = ((size_t)wid * NH + head) * (64 * HD);
    const float* qg = g_q + base;
    const float* kg = g_k + base;
    const float* vg = g_v + base;

    #pragma unroll
    for (int s4 = 0; s4 < 2; s4++) {
        int e = tid + s4 * 256;
        int n = e >> 3, d4 = e & 7;
        float4 v; uint2 ph, pl;
        v = *reinterpret_cast<const float4*>(qg + e * 4);
        v.x *= WSCALE; v.y *= WSCALE; v.z *= WSCALE; v.w *= WSCALE;
        split_pack(v, ph, pl);
        *reinterpret_cast<uint2*>(smb + n * ASA + d4 * 4)        = ph;
        *reinterpret_cast<uint2*>(smb + 2560 + n * ASA + d4 * 4) = pl;
        v = *reinterpret_cast<const float4*>(kg + e * 4);
        split_pack(v, ph, pl);
        *reinterpret_cast<uint2*>(smb + 5120 + n * ASA + d4 * 4) = ph;
        *reinterpret_cast<uint2*>(smb + 7680 + n * ASA + d4 * 4) = pl;
        v = *reinterpret_cast<const float4*>(vg + e * 4);
        split_pack(v, ph, pl);
        *reinterpret_cast<uint2*>(smb + 10240 + n * ASA + d4 * 4) = ph;
        *reinterpret_cast<uint2*>(smb + 12800 + n * ASA + d4 * 4) = pl;
    }
    __syncthreads();

    // S = Q K^T : 16 frags of 16x16, 2 per warp
    #pragma unroll
    for (int fi = 0; fi < 2; fi++) {
        int f = warp + fi * 8;
        int mi = f >> 2, ni = f & 3;
        wmma::fragment<wmma::accumulator, 16, 16, 16, float> acc;
        wmma::fill_fragment(acc, 0.0f);
        #pragma unroll
        for (int ks = 0; ks < 2; ks++) {
            wmma::fragment<wmma::matrix_a, 16, 16, 16, bf16, wmma::row_major> fah, fal;
            wmma::fragment<wmma::matrix_b, 16, 16, 16, bf16, wmma::col_major> fbh, fbl;
            wmma::load_matrix_sync(fah, smb + (mi * 16) * ASA + ks * 16, ASA);
            wmma::load_matrix_sync(fal, smb + 2560 + (mi * 16) * ASA + ks * 16, ASA);
            wmma::load_matrix_sync(fbh, smb + 5120 + (ni * 16) * ASA + ks * 16, ASA);
            wmma::load_matrix_sync(fbl, smb + 7680 + (ni * 16) * ASA + ks * 16, ASA);
            wmma::mma_sync(acc, fah, fbh, acc);
            wmma::mma_sync(acc, fah, fbl, acc);
            wmma::mma_sync(acc, fal, fbh, acc);
        }
        wmma::store_matrix_sync(s + (mi * 16) * SC + ni * 16, acc, SC, wmma::mem_row_major);
    }
    __syncthreads();

    // Row softmax: 4 threads per row, shfl reduce
    {
        int row = tid >> 2, l4 = tid & 3;
        float* sr = s + row * SC;
        float m = -1e30f;
        #pragma unroll
        for (int c = 0; c < 16; c++) m = fmaxf(m, sr[l4 * 16 + c]);
        m = fmaxf(m, __shfl_xor_sync(0xFFFFFFFF, m, 1));
        m = fmaxf(m, __shfl_xor_sync(0xFFFFFFFF, m, 2));
        float sum = 0.f;
        float e[16];
        #pragma unroll
        for (int c = 0; c < 16; c++) { e[c] = expf(sr[l4 * 16 + c] - m); sum += e[c]; }
        sum += __shfl_xor_sync(0xFFFFFFFF, sum, 1);
        sum += __shfl_xor_sync(0xFFFFFFFF, sum, 2);
        float inv = 1.f / sum;
        #pragma unroll
        for (int c = 0; c < 16; c++) {
            float a = e[c] * inv;
            bf16 h = __float2bfloat16(a);
            ah[row * 72 + l4 * 16 + c] = h;
            al[row * 72 + l4 * 16 + c] = __float2bfloat16(a - __bfloat162float(h));
        }
    }
    __syncthreads();

    // O = A V : 8 frags (4x2), one per warp; stage f32 to smem
    {
        int mi = warp >> 1, ni = warp & 1;
        wmma::fragment<wmma::accumulator, 16, 16, 16, float> acc;
        wmma::fill_fragment(acc, 0.0f);
        #pragma unroll
        for (int ks = 0; ks < 4; ks++) {
            wmma::fragment<wmma::matrix_a, 16, 16, 16, bf16, wmma::row_major> fah, fal;
            wmma::fragment<wmma::matrix_b, 16, 16, 16, bf16, wmma::row_major> fbh, fbl;
            wmma::load_matrix_sync(fah, ah + (mi * 16) * 72 + ks * 16, 72);
            wmma::load_matrix_sync(fal, al + (mi * 16) * 72 + ks * 16, 72);
            wmma::load_matrix_sync(fbh, smb + 10240 + (ks * 16) * ASA + ni * 16, ASA);
            wmma::load_matrix_sync(fbl, smb + 12800 + (ks * 16) * ASA + ni * 16, ASA);
            wmma::mma_sync(acc, fah, fbh, acc);
            wmma::mma_sync(acc, fah, fbl, acc);
            wmma::mma_sync(acc, fal, fbh, acc);
        }
        wmma::store_matrix_sync(s + (mi * 16) * 36 + ni * 16, acc, 36, wmma::mem_row_major);
    }
    __syncthreads();

    // O -> g_aoh fp16 single (uint4 = 8 halves); rows windowed, cols head*32..+31
    {
        int row = tid >> 2, c8 = (tid & 3) * 8;
        float4 v0 = *reinterpret_cast<const float4*>(s + row * 36 + c8);
        float4 v1 = *reinterpret_cast<const float4*>(s + row * 36 + c8 + 4);
        size_t di = (size_t)(wid * 64 + row) * 64 + head * 4 + (tid & 3);
        g_aoh[di] = pack8_fp16(v0, v1);
    }
}

extern "C" void kernel_launch(void* const* d_in, const int* in_sizes, int n_in,
                              void* d_out, int out_size)
{
    (void)in_sizes; (void)n_in; (void)out_size;
    const float* x      = (const float*)d_in[0];
    const float* qkv_w  = (const float*)d_in[1];
    const float* qkv_b  = (const float*)d_in[2];
    // d_in[3], d_in[4] (kv_w, kv_b) are dead code in the reference output
    const float* proj_w = (const float*)d_in[5];
    const float* proj_b = (const float*)d_in[6];
    float* out = (float*)d_out;

    const int gemm_smem = 2 * STAGE_B;            // 73728 B
    const int attn_smem = 30720 + 64 * SC * 4;    // 48128 B

    cudaFuncSetAttribute(gemm_kernel<true>,
                         cudaFuncAttributeMaxDynamicSharedMemorySize, gemm_smem);
    cudaFuncSetAttribute(gemm_kernel<false>,
                         cudaFuncAttributeMaxDynamicSharedMemorySize, gemm_smem);

    split_x_kernel<<<NTOK * DIM / 8 / 256, 256>>>(x);
    split_w_kernel<<<DIM * NQKV / 8 / 256, 256>>>(qkv_w, 0);
    split_w_kernel<<<DIM * DIM  / 8 / 256, 256>>>(proj_w, 1);

    gemm_kernel<true>
        <<<dim3(NTOK / BM, NQKV / BN), 256, gemm_smem>>>(qkv_b, nullptr);
    attn_kernel<<<dim3(NWIN, NH), 256, attn_smem>>>();
    gemm_kernel<false>
        <<<dim3(NTOK / BM, DIM / BN), 256, gemm_smem>>>(proj_b, out);
}